// round 13
// baseline (speedup 1.0000x reference)
#include <cuda_runtime.h>
#include <math.h>

// ---------------- problem constants ----------------
// B=16, T=512, F=229, C1=48, C3=96, T2=510, HID=768, P=88, NCLS=5
#define NCTA 128
#define NTHR 384
#define NWARPS (NCTA*12)

typedef unsigned long long ull;

// ---------------- static device scratch ----------------
__device__ __align__(16) float g_A [90046464];   // conv1 out (16,48,512,229)
__device__ __align__(16) float g_Cb[44826624];   // conv2+pool out (16,48,512,114)
__device__ __align__(16) float g_D [44651520];   // conv3+pool out (8160, 5472)
__device__ __align__(16) float g_ac[ 6266880];   // acoustic (8160, 768)
__device__ __align__(16) float g_Z [25067520];   // ac@wih0[:, :768]^T + biases (8160, 3072)
__device__ __align__(16) float g_h1[2][16*768];
__device__ __align__(16) float g_h2[2][16*768];
__device__ __align__(16) float g_c1[16*768];
__device__ __align__(16) float g_c2[16*768];
__device__ __align__(16) float g_prev[16*176];

// grid-barrier state (persists across launches; monotonic)
__device__ unsigned g_gen;        // #barriers completed so far (zero-init)
__device__ unsigned g_count;      // monotonic arrival counter (zero-init) — atomics only
__device__ unsigned g_release;    // published generation (zero-init) — 1 write + reads only

// ---- f32x2 packed helpers (elementwise .rn — bit-identical per-lane math) ----
__device__ __forceinline__ ull pk2(float lo, float hi) {
    ull r; asm("mov.b64 %0, {%1, %2};" : "=l"(r) : "f"(lo), "f"(hi)); return r;
}
__device__ __forceinline__ void fma2(ull& acc, ull a, ull b) {
    asm("fma.rn.f32x2 %0, %1, %2, %3;" : "=l"(acc) : "l"(a), "l"(b), "l"(acc));
}
__device__ __forceinline__ void add2(ull& acc, ull o) {
    asm("add.rn.f32x2 %0, %1, %2;" : "=l"(acc) : "l"(acc), "l"(o));
}
__device__ __forceinline__ void upk2(float& lo, float& hi, ull v) {
    asm("mov.b64 {%0, %1}, %2;" : "=f"(lo), "=f"(hi) : "l"(v));
}

// =================== conv1 + bn1 + relu ===================
__global__ __launch_bounds__(256) void k_conv1(
    const float* __restrict__ mel, const float* __restrict__ w,
    const float* __restrict__ cb,  const float* __restrict__ bg,
    const float* __restrict__ bb,  const float* __restrict__ bm,
    const float* __restrict__ bv)
{
    __shared__ float sw[48*9];
    __shared__ float sA[48], sB[48];
    int tid = threadIdx.x;
    for (int i = tid; i < 48*9; i += 256) sw[i] = w[i];
    if (tid < 48) {
        float s = bg[tid] * rsqrtf(bv[tid] + 1e-5f);
        sA[tid] = s;
        sB[tid] = cb[tid]*s + bb[tid] - bm[tid]*s;
    }
    __syncthreads();
    int idx = blockIdx.x*256 + tid;
    if (idx >= 16*512*229) return;
    int wq = idx % 229; int h = (idx/229) % 512; int b = idx/(229*512);
    float in[9];
    #pragma unroll
    for (int ky = 0; ky < 3; ky++)
      #pragma unroll
      for (int kx = 0; kx < 3; kx++) {
        int ih = h-1+ky, iw = wq-1+kx;
        in[ky*3+kx] = (ih>=0 && ih<512 && iw>=0 && iw<229)
                      ? mel[(b*512+ih)*229 + iw] : 0.f;
      }
    for (int c = 0; c < 48; c++) {
        float acc = 0.f;
        #pragma unroll
        for (int t9 = 0; t9 < 9; t9++) acc = fmaf(in[t9], sw[c*9+t9], acc);
        float v = fmaf(acc, sA[c], sB[c]);
        g_A[((b*48+c)*512+h)*229 + wq] = v > 0.f ? v : 0.f;
    }
}

// =================== conv2 + bn2 + relu + pool(1,2) ===================
__global__ __launch_bounds__(256) void k_conv2pool(
    const float* __restrict__ w2, const float* __restrict__ cb,
    const float* __restrict__ bg, const float* __restrict__ bb,
    const float* __restrict__ bm, const float* __restrict__ bv)
{
    __shared__ __align__(16) float s_in[12*3*232];
    __shared__ float4 s_w4[12*12*3];
    int tid = threadIdx.x;
    int gid = blockIdx.x;
    int cg = gid & 3; int h = (gid>>2) & 511; int b = gid >> 11;
    int wp = tid % 114, cs = tid / 114;
    ull acc2[6];
    #pragma unroll
    for (int m = 0; m < 6; m++) acc2[m] = 0ull;

    for (int ch = 0; ch < 4; ch++) {
        int ci0 = ch * 12;
        __syncthreads();
        for (int i = tid; i < 12*3*232; i += 256) {
            int ci = i/(3*232); int r = i%(3*232); int ky = r/232; int wc = r%232;
            int ih = h-1+ky; int iw = wc-1;
            float v = 0.f;
            if (ih >= 0 && ih < 512 && iw >= 0 && iw < 229)
                v = g_A[((b*48 + ci0+ci)*512 + ih)*229 + iw];
            s_in[(ci*3+ky)*232 + wc] = v;
        }
        {
            float* sw = (float*)s_w4;
            for (int i = tid; i < 12*12*9; i += 256) {
                int cc = i/108; int r = i%108; int ci = r/9; int t9 = r%9;
                int ky = t9/3, kx = t9%3;
                int c = cg*12 + cc;
                sw[((cc*12+ci)*3+ky)*4 + kx] = w2[((c*48 + ci0+ci)*3 + ky)*3 + kx];
            }
        }
        __syncthreads();
        if (tid < 228) {
            #pragma unroll 4
            for (int ci = 0; ci < 12; ci++) {
                #pragma unroll
                for (int ky = 0; ky < 3; ky++) {
                    const float2* row = (const float2*)&s_in[(ci*3+ky)*232 + 2*wp];
                    float2 fa = row[0], fb = row[1];
                    ull x0 = pk2(fa.x, fa.y);
                    ull x1 = pk2(fa.y, fb.x);
                    ull x2 = pk2(fb.x, fb.y);
                    #pragma unroll
                    for (int m = 0; m < 6; m++) {
                        float4 wv = s_w4[((cs+2*m)*12 + ci)*3 + ky];
                        fma2(acc2[m], x0, pk2(wv.x, wv.x));
                        fma2(acc2[m], x1, pk2(wv.y, wv.y));
                        fma2(acc2[m], x2, pk2(wv.z, wv.z));
                    }
                }
            }
        }
    }
    if (tid < 228) {
        #pragma unroll
        for (int m = 0; m < 6; m++) {
            int c = cg*12 + cs + 2*m;
            float s = bg[c] * rsqrtf(bv[c] + 1e-5f);
            float t = cb[c]*s + bb[c] - bm[c]*s;
            float a0, a1; upk2(a0, a1, acc2[m]);
            float v = fmaxf(fmaxf(fmaf(a0,s,t), fmaf(a1,s,t)), 0.f);
            g_Cb[((b*48+c)*512+h)*114 + wp] = v;
        }
    }
}

// =================== conv3 + bn3 + relu + pool(1,2) ===================
__global__ __launch_bounds__(256) void k_conv3pool(
    const float* __restrict__ w3, const float* __restrict__ cb,
    const float* __restrict__ bg, const float* __restrict__ bb,
    const float* __restrict__ bm, const float* __restrict__ bv)
{
    __shared__ __align__(16) float s_in[12*3*120];
    __shared__ float4 s_w4[12*12*3];
    int tid = threadIdx.x;
    int gid = blockIdx.x;
    int cg = gid & 7; int t = (gid>>3) % 510; int b = gid / (510*8);
    int wp = tid % 57, cs = tid / 57;
    ull acc2[3];
    #pragma unroll
    for (int m = 0; m < 3; m++) acc2[m] = 0ull;

    for (int ch = 0; ch < 4; ch++) {
        int ci0 = ch * 12;
        __syncthreads();
        for (int i = tid; i < 12*3*120; i += 256) {
            int ci = i/360; int r = i%360; int ky = r/120; int wc = r%120;
            int ih = t + ky; int iw = wc - 1;
            float v = 0.f;
            if (iw >= 0 && iw < 114)
                v = g_Cb[((b*48 + ci0+ci)*512 + ih)*114 + iw];
            s_in[(ci*3+ky)*120 + wc] = v;
        }
        {
            float* sw = (float*)s_w4;
            for (int i = tid; i < 12*12*9; i += 256) {
                int cc = i/108; int r = i%108; int ci = r/9; int t9 = r%9;
                int ky = t9/3, kx = t9%3;
                int c = cg*12 + cc;
                sw[((cc*12+ci)*3+ky)*4 + kx] = w3[((c*48 + ci0+ci)*3 + ky)*3 + kx];
            }
        }
        __syncthreads();
        if (tid < 228) {
            #pragma unroll 4
            for (int ci = 0; ci < 12; ci++) {
                #pragma unroll
                for (int ky = 0; ky < 3; ky++) {
                    const float2* row = (const float2*)&s_in[(ci*3+ky)*120 + 2*wp];
                    float2 fa = row[0], fb = row[1];
                    ull x0 = pk2(fa.x, fa.y);
                    ull x1 = pk2(fa.y, fb.x);
                    ull x2 = pk2(fb.x, fb.y);
                    #pragma unroll
                    for (int m = 0; m < 3; m++) {
                        float4 wv = s_w4[((cs+4*m)*12 + ci)*3 + ky];
                        fma2(acc2[m], x0, pk2(wv.x, wv.x));
                        fma2(acc2[m], x1, pk2(wv.y, wv.y));
                        fma2(acc2[m], x2, pk2(wv.z, wv.z));
                    }
                }
            }
        }
    }
    if (tid < 228) {
        #pragma unroll
        for (int m = 0; m < 3; m++) {
            int c = cg*12 + cs + 4*m;
            float s = bg[c] * rsqrtf(bv[c] + 1e-5f);
            float tt = cb[c]*s + bb[c] - bm[c]*s;
            float a0, a1; upk2(a0, a1, acc2[m]);
            float v = fmaxf(fmaxf(fmaf(a0,s,tt), fmaf(a1,s,tt)), 0.f);
            g_D[(b*510+t)*5472 + c*57 + wp] = v;
        }
    }
}

// =================== FC GEMM: acoustic = g_D @ fcw^T + fcb ===================
__global__ __launch_bounds__(256) void k_fc(
    const float* __restrict__ fcw, const float* __restrict__ fcb)
{
    __shared__ float As[16][64];
    __shared__ float Bs[16][64];
    int tid = threadIdx.x;
    int n0 = blockIdx.x * 64, m0 = blockIdx.y * 64;
    int arow = tid >> 2, k4 = (tid & 3) * 4;
    int msub = (tid >> 4) * 4, nsub = (tid & 15) * 4;
    float acc[4][4] = {};
    for (int kt = 0; kt < 342; kt++) {
        int k0 = kt * 16;
        float4 av = make_float4(0.f,0.f,0.f,0.f);
        int m = m0 + arow;
        if (m < 8160) av = *(const float4*)&g_D[m*5472 + k0 + k4];
        float4 bv = *(const float4*)&fcw[(n0+arow)*5472 + k0 + k4];
        __syncthreads();
        As[k4+0][arow]=av.x; As[k4+1][arow]=av.y; As[k4+2][arow]=av.z; As[k4+3][arow]=av.w;
        Bs[k4+0][arow]=bv.x; Bs[k4+1][arow]=bv.y; Bs[k4+2][arow]=bv.z; Bs[k4+3][arow]=bv.w;
        __syncthreads();
        #pragma unroll
        for (int k = 0; k < 16; k++) {
            float4 a4 = *(const float4*)&As[k][msub];
            float4 b4 = *(const float4*)&Bs[k][nsub];
            acc[0][0]=fmaf(a4.x,b4.x,acc[0][0]); acc[0][1]=fmaf(a4.x,b4.y,acc[0][1]);
            acc[0][2]=fmaf(a4.x,b4.z,acc[0][2]); acc[0][3]=fmaf(a4.x,b4.w,acc[0][3]);
            acc[1][0]=fmaf(a4.y,b4.x,acc[1][0]); acc[1][1]=fmaf(a4.y,b4.y,acc[1][1]);
            acc[1][2]=fmaf(a4.y,b4.z,acc[1][2]); acc[1][3]=fmaf(a4.y,b4.w,acc[1][3]);
            acc[2][0]=fmaf(a4.z,b4.x,acc[2][0]); acc[2][1]=fmaf(a4.z,b4.y,acc[2][1]);
            acc[2][2]=fmaf(a4.z,b4.z,acc[2][2]); acc[2][3]=fmaf(a4.z,b4.w,acc[2][3]);
            acc[3][0]=fmaf(a4.w,b4.x,acc[3][0]); acc[3][1]=fmaf(a4.w,b4.y,acc[3][1]);
            acc[3][2]=fmaf(a4.w,b4.z,acc[3][2]); acc[3][3]=fmaf(a4.w,b4.w,acc[3][3]);
        }
    }
    float b0=fcb[n0+nsub], b1=fcb[n0+nsub+1], b2=fcb[n0+nsub+2], b3=fcb[n0+nsub+3];
    #pragma unroll
    for (int i = 0; i < 4; i++) {
        int m = m0 + msub + i;
        if (m < 8160) {
            g_ac[m*768 + n0+nsub+0] = acc[i][0] + b0;
            g_ac[m*768 + n0+nsub+1] = acc[i][1] + b1;
            g_ac[m*768 + n0+nsub+2] = acc[i][2] + b2;
            g_ac[m*768 + n0+nsub+3] = acc[i][3] + b3;
        }
    }
}

// ====== Z GEMM: g_Z = g_ac @ wih0[:, :768]^T + bih0 + bhh0  (8160 x 3072 x 768) ======
__global__ __launch_bounds__(256) void k_zg(
    const float* __restrict__ wih0,
    const float* __restrict__ bih0, const float* __restrict__ bhh0)
{
    __shared__ float As[16][64];
    __shared__ float Bs[16][64];
    int tid = threadIdx.x;
    int n0 = blockIdx.x * 64, m0 = blockIdx.y * 64;
    int arow = tid >> 2, k4 = (tid & 3) * 4;
    int msub = (tid >> 4) * 4, nsub = (tid & 15) * 4;
    float acc[4][4] = {};
    for (int kt = 0; kt < 48; kt++) {
        int k0 = kt * 16;
        float4 av = make_float4(0.f,0.f,0.f,0.f);
        int m = m0 + arow;
        if (m < 8160) av = *(const float4*)&g_ac[m*768 + k0 + k4];
        float4 bv = *(const float4*)&wih0[(n0+arow)*944 + k0 + k4];
        __syncthreads();
        As[k4+0][arow]=av.x; As[k4+1][arow]=av.y; As[k4+2][arow]=av.z; As[k4+3][arow]=av.w;
        Bs[k4+0][arow]=bv.x; Bs[k4+1][arow]=bv.y; Bs[k4+2][arow]=bv.z; Bs[k4+3][arow]=bv.w;
        __syncthreads();
        #pragma unroll
        for (int k = 0; k < 16; k++) {
            float4 a4 = *(const float4*)&As[k][msub];
            float4 b4 = *(const float4*)&Bs[k][nsub];
            acc[0][0]=fmaf(a4.x,b4.x,acc[0][0]); acc[0][1]=fmaf(a4.x,b4.y,acc[0][1]);
            acc[0][2]=fmaf(a4.x,b4.z,acc[0][2]); acc[0][3]=fmaf(a4.x,b4.w,acc[0][3]);
            acc[1][0]=fmaf(a4.y,b4.x,acc[1][0]); acc[1][1]=fmaf(a4.y,b4.y,acc[1][1]);
            acc[1][2]=fmaf(a4.y,b4.z,acc[1][2]); acc[1][3]=fmaf(a4.y,b4.w,acc[1][3]);
            acc[2][0]=fmaf(a4.z,b4.x,acc[2][0]); acc[2][1]=fmaf(a4.z,b4.y,acc[2][1]);
            acc[2][2]=fmaf(a4.z,b4.z,acc[2][2]); acc[2][3]=fmaf(a4.z,b4.w,acc[2][3]);
            acc[3][0]=fmaf(a4.w,b4.x,acc[3][0]); acc[3][1]=fmaf(a4.w,b4.y,acc[3][1]);
            acc[3][2]=fmaf(a4.w,b4.z,acc[3][2]); acc[3][3]=fmaf(a4.w,b4.w,acc[3][3]);
        }
    }
    int nn = n0 + nsub;
    float b0=bih0[nn]+bhh0[nn], b1=bih0[nn+1]+bhh0[nn+1];
    float b2=bih0[nn+2]+bhh0[nn+2], b3=bih0[nn+3]+bhh0[nn+3];
    #pragma unroll
    for (int i = 0; i < 4; i++) {
        int m = m0 + msub + i;
        if (m < 8160) {
            g_Z[m*3072 + nn+0] = acc[i][0] + b0;
            g_Z[m*3072 + nn+1] = acc[i][1] + b1;
            g_Z[m*3072 + nn+2] = acc[i][2] + b2;
            g_Z[m*3072 + nn+3] = acc[i][3] + b3;
        }
    }
}

// =================== persistent LSTM scan ===================
__device__ __forceinline__ float sigf(float x) { return 1.f/(1.f+expf(-x)); }

// Split-flag grid barrier:
//   arrivals: atom.acq_rel.add on g_count (atomics ONLY — no poll traffic)
//   last arriver publishes g_release = nbar with st.release.gpu
//   other 127 leaders poll g_release (clean line: 1 write/barrier + reads)
__device__ __forceinline__ void gbar(unsigned nbar) {
    __threadfence();
    __syncthreads();
    if (threadIdx.x == 0) {
        unsigned old;
        asm volatile("atom.acq_rel.gpu.global.add.u32 %0, [%1], %2;"
                     : "=r"(old) : "l"(&g_count), "r"(1u) : "memory");
        if (old == nbar*NCTA - 1u) {
            asm volatile("st.release.gpu.global.u32 [%0], %1;"
                         :: "l"(&g_release), "r"(nbar) : "memory");
        } else {
            unsigned v;
            do {
                asm volatile("ld.acquire.gpu.global.u32 %0, [%1];"
                             : "=r"(v) : "l"(&g_release) : "memory");
            } while ((int)(v - nbar) < 0);
        }
    }
    __syncthreads();
}

__global__ __launch_bounds__(NTHR, 1) void k_lstm(
    const float* __restrict__ wih0, const float* __restrict__ whh0,
    const float* __restrict__ wih1, const float* __restrict__ whh1,
    const float* __restrict__ bih1, const float* __restrict__ bhh1,
    const float* __restrict__ pw,   const float* __restrict__ pb,
    const float* __restrict__ emb,  float* __restrict__ out)
{
    extern __shared__ __align__(16) ull su[];       // 12288 ull = 98304 B
    int tid = threadIdx.x;
    int cta = blockIdx.x;
    int warp = tid >> 5, lane = tid & 31;
    int gw = cta*12 + warp;                          // 0..1535: one task per warp

    const float4* wih04 = (const float4*)wih0;   // rows of 236 float4
    const float4* whh04 = (const float4*)whh0;   // rows of 192 float4
    const float4* wih14 = (const float4*)wih1;   // rows of 192 float4
    const float4* whh14 = (const float4*)whh1;   // rows of 192 float4
    const float4* pw4   = (const float4*)pw;     // rows of 192 float4

    int jt = gw >> 1;                  // hidden unit
    int b0 = (gw & 1) * 8;             // batch half base
    int p0 = (gw & 1) * 4;             // global pair base

    unsigned bt = g_gen;

    // ---- init state (both parity banks) ----
    {
        int i = cta*NTHR + tid;
        if (i < 12288) {
            g_h1[0][i] = 0.f; g_h1[1][i] = 0.f;
            g_h2[0][i] = 0.f; g_h2[1][i] = 0.f;
            g_c1[i] = 0.f;    g_c2[i] = 0.f;
        }
        if (i < 2816) g_prev[i] = 0.f;
    }
    bt++; gbar(bt);

    for (int t = 0; t < 510; t++) {
        int r = t & 1;
        float* h1new = g_h1[1-r];
        float* h2new = g_h2[1-r];

        // ===== phase A: layer-1 gates (K = prev(44) + h1old(192) = 236 fl4; ac part in g_Z) =====
        for (int i = tid; i < 8*236; i += NTHR) {
            int pg = i / 236, c = i - pg*236;
            int ba = 2*pg, bbq = ba+1;
            float4 a0, a1;
            if (c < 44) {
                a0 = __ldcg((const float4*)&g_prev[ba*176] + c);
                a1 = __ldcg((const float4*)&g_prev[bbq*176] + c);
            } else {
                a0 = __ldcg((const float4*)&g_h1[r][ba*768] + (c-44));
                a1 = __ldcg((const float4*)&g_h1[r][bbq*768] + (c-44));
            }
            int base = i*4;
            su[base+0] = pk2(a0.x, a1.x);
            su[base+1] = pk2(a0.y, a1.y);
            su[base+2] = pk2(a0.z, a1.z);
            su[base+3] = pk2(a0.w, a1.w);
        }
        __syncthreads();

        {
            ull acc2[4][4];
            #pragma unroll
            for (int g = 0; g < 4; g++)
                #pragma unroll
                for (int pl = 0; pl < 4; pl++) acc2[g][pl] = 0ull;

            float z4[4];
            if (lane < 8) {
                int m = (b0 + lane)*510 + t;
                #pragma unroll
                for (int g = 0; g < 4; g++)
                    z4[g] = __ldg(&g_Z[m*3072 + g*768 + jt]);
            }

            for (int c = lane; c < 236; c += 32) {
                float4 w0, w1, w2, w3;
                if (c < 44) {
                    int cc = 192 + c;
                    w0 = __ldg(&wih04[(jt       )*236 + cc]);
                    w1 = __ldg(&wih04[(jt +  768)*236 + cc]);
                    w2 = __ldg(&wih04[(jt + 1536)*236 + cc]);
                    w3 = __ldg(&wih04[(jt + 2304)*236 + cc]);
                } else {
                    int cc = c - 44;
                    w0 = __ldg(&whh04[(jt       )*192 + cc]);
                    w1 = __ldg(&whh04[(jt +  768)*192 + cc]);
                    w2 = __ldg(&whh04[(jt + 1536)*192 + cc]);
                    w3 = __ldg(&whh04[(jt + 2304)*192 + cc]);
                }
                ull X[4][4];
                #pragma unroll
                for (int pl = 0; pl < 4; pl++) {
                    int base = ((p0+pl)*236 + c)*4;
                    ulonglong2 xa = *(const ulonglong2*)&su[base];
                    ulonglong2 xb = *(const ulonglong2*)&su[base+2];
                    X[pl][0]=xa.x; X[pl][1]=xa.y; X[pl][2]=xb.x; X[pl][3]=xb.y;
                }
                {
                    ull d0=pk2(w0.x,w0.x), d1=pk2(w0.y,w0.y), d2=pk2(w0.z,w0.z), d3=pk2(w0.w,w0.w);
                    #pragma unroll
                    for (int pl = 0; pl < 4; pl++) {
                        fma2(acc2[0][pl], X[pl][0], d0); fma2(acc2[0][pl], X[pl][1], d1);
                        fma2(acc2[0][pl], X[pl][2], d2); fma2(acc2[0][pl], X[pl][3], d3);
                    }
                }
                {
                    ull d0=pk2(w1.x,w1.x), d1=pk2(w1.y,w1.y), d2=pk2(w1.z,w1.z), d3=pk2(w1.w,w1.w);
                    #pragma unroll
                    for (int pl = 0; pl < 4; pl++) {
                        fma2(acc2[1][pl], X[pl][0], d0); fma2(acc2[1][pl], X[pl][1], d1);
                        fma2(acc2[1][pl], X[pl][2], d2); fma2(acc2[1][pl], X[pl][3], d3);
                    }
                }
                {
                    ull d0=pk2(w2.x,w2.x), d1=pk2(w2.y,w2.y), d2=pk2(w2.z,w2.z), d3=pk2(w2.w,w2.w);
                    #pragma unroll
                    for (int pl = 0; pl < 4; pl++) {
                        fma2(acc2[2][pl], X[pl][0], d0); fma2(acc2[2][pl], X[pl][1], d1);
                        fma2(acc2[2][pl], X[pl][2], d2); fma2(acc2[2][pl], X[pl][3], d3);
                    }
                }
                {
                    ull d0=pk2(w3.x,w3.x), d1=pk2(w3.y,w3.y), d2=pk2(w3.z,w3.z), d3=pk2(w3.w,w3.w);
                    #pragma unroll
                    for (int pl = 0; pl < 4; pl++) {
                        fma2(acc2[3][pl], X[pl][0], d0); fma2(acc2[3][pl], X[pl][1], d1);
                        fma2(acc2[3][pl], X[pl][2], d2); fma2(acc2[3][pl], X[pl][3], d3);
                    }
                }
            }
            #pragma unroll
            for (int off = 16; off; off >>= 1)
                #pragma unroll
                for (int g = 0; g < 4; g++)
                    #pragma unroll
                    for (int pl = 0; pl < 4; pl++) {
                        ull o = __shfl_xor_sync(0xffffffffu, acc2[g][pl], off);
                        add2(acc2[g][pl], o);
                    }
            if (lane < 8) {
                int pl = lane >> 1, hb = lane & 1;
                float zz[4];
                #pragma unroll
                for (int g = 0; g < 4; g++) {
                    float lo, hi; upk2(lo, hi, acc2[g][pl]);
                    zz[g] = (hb ? hi : lo) + z4[g];
                }
                int hi_ = (b0 + lane)*768 + jt;
                float c_ = sigf(zz[1])*g_c1[hi_] + sigf(zz[0])*tanhf(zz[2]);
                g_c1[hi_] = c_;
                h1new[hi_] = sigf(zz[3])*tanhf(c_);
            }
        }
        bt++; gbar(bt);

        // ===== phase B: layer-2 gates (K = h1new(192) + h2old(192) = 384 fl4) =====
        for (int i = tid; i < 8*384; i += NTHR) {
            int pg = i / 384, c = i - pg*384;
            int ba = 2*pg, bbq = ba+1;
            float4 a0, a1;
            if (c < 192) {
                a0 = __ldcg((const float4*)&h1new[ba*768] + c);
                a1 = __ldcg((const float4*)&h1new[bbq*768] + c);
            } else {
                a0 = __ldcg((const float4*)&g_h2[r][ba*768] + (c-192));
                a1 = __ldcg((const float4*)&g_h2[r][bbq*768] + (c-192));
            }
            int base = i*4;
            su[base+0] = pk2(a0.x, a1.x);
            su[base+1] = pk2(a0.y, a1.y);
            su[base+2] = pk2(a0.z, a1.z);
            su[base+3] = pk2(a0.w, a1.w);
        }
        __syncthreads();

        {
            ull acc2[4][4];
            #pragma unroll
            for (int g = 0; g < 4; g++)
                #pragma unroll
                for (int pl = 0; pl < 4; pl++) acc2[g][pl] = 0ull;

            float bsum[4];
            if (lane < 8) {
                #pragma unroll
                for (int g = 0; g < 4; g++)
                    bsum[g] = __ldg(&bih1[jt + g*768]) + __ldg(&bhh1[jt + g*768]);
            }

            for (int c = lane; c < 384; c += 32) {
                float4 w0, w1, w2, w3;
                if (c < 192) {
                    w0 = __ldg(&wih14[(jt       )*192 + c]);
                    w1 = __ldg(&wih14[(jt +  768)*192 + c]);
                    w2 = __ldg(&wih14[(jt + 1536)*192 + c]);
                    w3 = __ldg(&wih14[(jt + 2304)*192 + c]);
                } else {
                    int cc = c - 192;
                    w0 = __ldg(&whh14[(jt       )*192 + cc]);
                    w1 = __ldg(&whh14[(jt +  768)*192 + cc]);
                    w2 = __ldg(&whh14[(jt + 1536)*192 + cc]);
                    w3 = __ldg(&whh14[(jt + 2304)*192 + cc]);
                }
                ull X[4][4];
                #pragma unroll
                for (int pl = 0; pl < 4; pl++) {
                    int base = ((p0+pl)*384 + c)*4;
                    ulonglong2 xa = *(const ulonglong2*)&su[base];
                    ulonglong2 xb = *(const ulonglong2*)&su[base+2];
                    X[pl][0]=xa.x; X[pl][1]=xa.y; X[pl][2]=xb.x; X[pl][3]=xb.y;
                }
                {
                    ull d0=pk2(w0.x,w0.x), d1=pk2(w0.y,w0.y), d2=pk2(w0.z,w0.z), d3=pk2(w0.w,w0.w);
                    #pragma unroll
                    for (int pl = 0; pl < 4; pl++) {
                        fma2(acc2[0][pl], X[pl][0], d0); fma2(acc2[0][pl], X[pl][1], d1);
                        fma2(acc2[0][pl], X[pl][2], d2); fma2(acc2[0][pl], X[pl][3], d3);
                    }
                }
                {
                    ull d0=pk2(w1.x,w1.x), d1=pk2(w1.y,w1.y), d2=pk2(w1.z,w1.z), d3=pk2(w1.w,w1.w);
                    #pragma unroll
                    for (int pl = 0; pl < 4; pl++) {
                        fma2(acc2[1][pl], X[pl][0], d0); fma2(acc2[1][pl], X[pl][1], d1);
                        fma2(acc2[1][pl], X[pl][2], d2); fma2(acc2[1][pl], X[pl][3], d3);
                    }
                }
                {
                    ull d0=pk2(w2.x,w2.x), d1=pk2(w2.y,w2.y), d2=pk2(w2.z,w2.z), d3=pk2(w2.w,w2.w);
                    #pragma unroll
                    for (int pl = 0; pl < 4; pl++) {
                        fma2(acc2[2][pl], X[pl][0], d0); fma2(acc2[2][pl], X[pl][1], d1);
                        fma2(acc2[2][pl], X[pl][2], d2); fma2(acc2[2][pl], X[pl][3], d3);
                    }
                }
                {
                    ull d0=pk2(w3.x,w3.x), d1=pk2(w3.y,w3.y), d2=pk2(w3.z,w3.z), d3=pk2(w3.w,w3.w);
                    #pragma unroll
                    for (int pl = 0; pl < 4; pl++) {
                        fma2(acc2[3][pl], X[pl][0], d0); fma2(acc2[3][pl], X[pl][1], d1);
                        fma2(acc2[3][pl], X[pl][2], d2); fma2(acc2[3][pl], X[pl][3], d3);
                    }
                }
            }
            #pragma unroll
            for (int off = 16; off; off >>= 1)
                #pragma unroll
                for (int g = 0; g < 4; g++)
                    #pragma unroll
                    for (int pl = 0; pl < 4; pl++) {
                        ull o = __shfl_xor_sync(0xffffffffu, acc2[g][pl], off);
                        add2(acc2[g][pl], o);
                    }
            if (lane < 8) {
                int pl = lane >> 1, hb = lane & 1;
                float zz[4];
                #pragma unroll
                for (int g = 0; g < 4; g++) {
                    float lo, hi; upk2(lo, hi, acc2[g][pl]);
                    zz[g] = (hb ? hi : lo) + bsum[g];
                }
                int hi_ = (b0 + lane)*768 + jt;
                float c_ = sigf(zz[1])*g_c2[hi_] + sigf(zz[0])*tanhf(zz[2]);
                g_c2[hi_] = c_;
                h2new[hi_] = sigf(zz[3])*tanhf(c_);
            }
        }
        bt++; gbar(bt);

        // ===== phase C: projection + argmax + embedding feedback (direct L2 reads) =====
        if (gw < 1408) {
            int b = gw / 88, p = gw - b*88;
            const float4* h4 = (const float4*)&h2new[b*768];
            float a0=0.f, a1=0.f, a2=0.f, a3=0.f, a4=0.f;
            for (int c = lane; c < 192; c += 32) {
                float4 x = __ldcg(h4 + c);
                float4 v0 = __ldg(&pw4[(p*5+0)*192 + c]);
                float4 v1 = __ldg(&pw4[(p*5+1)*192 + c]);
                float4 v2 = __ldg(&pw4[(p*5+2)*192 + c]);
                float4 v3 = __ldg(&pw4[(p*5+3)*192 + c]);
                float4 v4 = __ldg(&pw4[(p*5+4)*192 + c]);
                a0 = fmaf(x.x,v0.x, fmaf(x.y,v0.y, fmaf(x.z,v0.z, fmaf(x.w,v0.w, a0))));
                a1 = fmaf(x.x,v1.x, fmaf(x.y,v1.y, fmaf(x.z,v1.z, fmaf(x.w,v1.w, a1))));
                a2 = fmaf(x.x,v2.x, fmaf(x.y,v2.y, fmaf(x.z,v2.z, fmaf(x.w,v2.w, a2))));
                a3 = fmaf(x.x,v3.x, fmaf(x.y,v3.y, fmaf(x.z,v3.z, fmaf(x.w,v3.w, a3))));
                a4 = fmaf(x.x,v4.x, fmaf(x.y,v4.y, fmaf(x.z,v4.z, fmaf(x.w,v4.w, a4))));
            }
            #pragma unroll
            for (int off = 16; off; off >>= 1) {
                a0 += __shfl_xor_sync(0xffffffffu, a0, off);
                a1 += __shfl_xor_sync(0xffffffffu, a1, off);
                a2 += __shfl_xor_sync(0xffffffffu, a2, off);
                a3 += __shfl_xor_sync(0xffffffffu, a3, off);
                a4 += __shfl_xor_sync(0xffffffffu, a4, off);
            }
            if (lane == 0) {
                float l0 = a0 + pb[p*5+0];
                float l1 = a1 + pb[p*5+1];
                float l2 = a2 + pb[p*5+2];
                float l3 = a3 + pb[p*5+3];
                float l4 = a4 + pb[p*5+4];
                float* o = &out[((b*510 + t)*88 + p)*5];
                o[0]=l0; o[1]=l1; o[2]=l2; o[3]=l3; o[4]=l4;
                float best = l0; int bi = 0;
                if (l1 > best) { best = l1; bi = 1; }
                if (l2 > best) { best = l2; bi = 2; }
                if (l3 > best) { best = l3; bi = 3; }
                if (l4 > best) { best = l4; bi = 4; }
                g_prev[b*176 + p*2]     = emb[bi*2];
                g_prev[b*176 + p*2 + 1] = emb[bi*2 + 1];
            }
        }
        bt++; gbar(bt);
    }

    if (cta == 0 && tid == 0) g_gen = bt;
}

// =================== host ===================
extern "C" void kernel_launch(void* const* d_in, const int* in_sizes, int n_in,
                              void* d_out, int out_size)
{
    const float* mel  = (const float*)d_in[0];
    const float* c1w  = (const float*)d_in[1];
    const float* c1b  = (const float*)d_in[2];
    const float* c2w  = (const float*)d_in[3];
    const float* c2b  = (const float*)d_in[4];
    const float* c3w  = (const float*)d_in[5];
    const float* c3b  = (const float*)d_in[6];
    const float* bn1g = (const float*)d_in[7],  *bn1b = (const float*)d_in[8];
    const float* bn1m = (const float*)d_in[9],  *bn1v = (const float*)d_in[10];
    const float* bn2g = (const float*)d_in[11], *bn2b = (const float*)d_in[12];
    const float* bn2m = (const float*)d_in[13], *bn2v = (const float*)d_in[14];
    const float* bn3g = (const float*)d_in[15], *bn3b = (const float*)d_in[16];
    const float* bn3m = (const float*)d_in[17], *bn3v = (const float*)d_in[18];
    const float* fcw  = (const float*)d_in[19], *fcb  = (const float*)d_in[20];
    const float* wih0 = (const float*)d_in[21], *whh0 = (const float*)d_in[22];
    const float* bih0 = (const float*)d_in[23], *bhh0 = (const float*)d_in[24];
    const float* wih1 = (const float*)d_in[25], *whh1 = (const float*)d_in[26];
    const float* bih1 = (const float*)d_in[27], *bhh1 = (const float*)d_in[28];
    const float* pw   = (const float*)d_in[29], *pb   = (const float*)d_in[30];
    const float* emb  = (const float*)d_in[31];
    float* out = (float*)d_out;

    cudaFuncSetAttribute((const void*)k_lstm,
                         cudaFuncAttributeMaxDynamicSharedMemorySize, 98304);

    k_conv1<<<(16*512*229 + 255)/256, 256>>>(mel, c1w, c1b, bn1g, bn1b, bn1m, bn1v);
    k_conv2pool<<<16*512*4, 256>>>(c2w, c2b, bn2g, bn2b, bn2m, bn2v);
    k_conv3pool<<<16*510*8, 256>>>(c3w, c3b, bn3g, bn3b, bn3m, bn3v);
    k_fc<<<dim3(12, 128), 256>>>(fcw, fcb);
    k_zg<<<dim3(48, 128), 256>>>(wih0, bih0, bhh0);
    k_lstm<<<NCTA, NTHR, 98304>>>(wih0, whh0, wih1, whh1,
                                  bih1, bhh1, pw, pb, emb, out);
}

// round 14
// speedup vs baseline: 1.0462x; 1.0462x over previous
#include <cuda_runtime.h>
#include <math.h>

// ---------------- problem constants ----------------
// B=16, T=512, F=229, C1=48, C3=96, T2=510, HID=768, P=88, NCLS=5
#define NCTA 128
#define NTHR 384
#define NWARPS (NCTA*12)

typedef unsigned long long ull;

// ---------------- static device scratch ----------------
__device__ __align__(16) float g_A [90046464];   // conv1 out (16,48,512,229)
__device__ __align__(16) float g_Cb[44826624];   // conv2+pool out (16,48,512,114)
__device__ __align__(16) float g_D [44651520];   // conv3+pool out (8160, 5472)
__device__ __align__(16) float g_ac[ 6266880];   // acoustic (8160, 768)
__device__ __align__(16) float g_Z [25067520];   // ac@wih0[:, :768]^T + biases (8160, 3072)
__device__ __align__(16) float g_h1[2][16*768];
__device__ __align__(16) float g_h2[2][16*768];
__device__ __align__(16) float g_c1[16*768];
__device__ __align__(16) float g_c2[16*768];
__device__ __align__(16) float g_prev[16*176];

// grid-barrier state (persists across launches; monotonic)
__device__ unsigned g_gen;      // #barriers completed so far (zero-init)
__device__ unsigned g_count;    // monotonic arrival counter (zero-init)

// ---- f32x2 packed helpers (elementwise .rn — bit-identical per-lane math) ----
__device__ __forceinline__ ull pk2(float lo, float hi) {
    ull r; asm("mov.b64 %0, {%1, %2};" : "=l"(r) : "f"(lo), "f"(hi)); return r;
}
__device__ __forceinline__ void fma2(ull& acc, ull a, ull b) {
    asm("fma.rn.f32x2 %0, %1, %2, %3;" : "=l"(acc) : "l"(a), "l"(b), "l"(acc));
}
__device__ __forceinline__ void add2(ull& acc, ull o) {
    asm("add.rn.f32x2 %0, %1, %2;" : "=l"(acc) : "l"(acc), "l"(o));
}
__device__ __forceinline__ void upk2(float& lo, float& hi, ull v) {
    asm("mov.b64 {%0, %1}, %2;" : "=f"(lo), "=f"(hi) : "l"(v));
}

// =================== conv1 + bn1 + relu ===================
__global__ __launch_bounds__(256) void k_conv1(
    const float* __restrict__ mel, const float* __restrict__ w,
    const float* __restrict__ cb,  const float* __restrict__ bg,
    const float* __restrict__ bb,  const float* __restrict__ bm,
    const float* __restrict__ bv)
{
    __shared__ float sw[48*9];
    __shared__ float sA[48], sB[48];
    int tid = threadIdx.x;
    for (int i = tid; i < 48*9; i += 256) sw[i] = w[i];
    if (tid < 48) {
        float s = bg[tid] * rsqrtf(bv[tid] + 1e-5f);
        sA[tid] = s;
        sB[tid] = cb[tid]*s + bb[tid] - bm[tid]*s;
    }
    __syncthreads();
    int idx = blockIdx.x*256 + tid;
    if (idx >= 16*512*229) return;
    int wq = idx % 229; int h = (idx/229) % 512; int b = idx/(229*512);
    float in[9];
    #pragma unroll
    for (int ky = 0; ky < 3; ky++)
      #pragma unroll
      for (int kx = 0; kx < 3; kx++) {
        int ih = h-1+ky, iw = wq-1+kx;
        in[ky*3+kx] = (ih>=0 && ih<512 && iw>=0 && iw<229)
                      ? mel[(b*512+ih)*229 + iw] : 0.f;
      }
    for (int c = 0; c < 48; c++) {
        float acc = 0.f;
        #pragma unroll
        for (int t9 = 0; t9 < 9; t9++) acc = fmaf(in[t9], sw[c*9+t9], acc);
        float v = fmaf(acc, sA[c], sB[c]);
        g_A[((b*48+c)*512+h)*229 + wq] = v > 0.f ? v : 0.f;
    }
}

// =================== conv2 + bn2 + relu + pool(1,2) ===================
__global__ __launch_bounds__(256) void k_conv2pool(
    const float* __restrict__ w2, const float* __restrict__ cb,
    const float* __restrict__ bg, const float* __restrict__ bb,
    const float* __restrict__ bm, const float* __restrict__ bv)
{
    __shared__ __align__(16) float s_in[12*3*232];
    __shared__ float4 s_w4[12*12*3];
    int tid = threadIdx.x;
    int gid = blockIdx.x;
    int cg = gid & 3; int h = (gid>>2) & 511; int b = gid >> 11;
    int wp = tid % 114, cs = tid / 114;
    ull acc2[6];
    #pragma unroll
    for (int m = 0; m < 6; m++) acc2[m] = 0ull;

    for (int ch = 0; ch < 4; ch++) {
        int ci0 = ch * 12;
        __syncthreads();
        for (int i = tid; i < 12*3*232; i += 256) {
            int ci = i/(3*232); int r = i%(3*232); int ky = r/232; int wc = r%232;
            int ih = h-1+ky; int iw = wc-1;
            float v = 0.f;
            if (ih >= 0 && ih < 512 && iw >= 0 && iw < 229)
                v = g_A[((b*48 + ci0+ci)*512 + ih)*229 + iw];
            s_in[(ci*3+ky)*232 + wc] = v;
        }
        {
            float* sw = (float*)s_w4;
            for (int i = tid; i < 12*12*9; i += 256) {
                int cc = i/108; int r = i%108; int ci = r/9; int t9 = r%9;
                int ky = t9/3, kx = t9%3;
                int c = cg*12 + cc;
                sw[((cc*12+ci)*3+ky)*4 + kx] = w2[((c*48 + ci0+ci)*3 + ky)*3 + kx];
            }
        }
        __syncthreads();
        if (tid < 228) {
            #pragma unroll 4
            for (int ci = 0; ci < 12; ci++) {
                #pragma unroll
                for (int ky = 0; ky < 3; ky++) {
                    const float2* row = (const float2*)&s_in[(ci*3+ky)*232 + 2*wp];
                    float2 fa = row[0], fb = row[1];
                    ull x0 = pk2(fa.x, fa.y);
                    ull x1 = pk2(fa.y, fb.x);
                    ull x2 = pk2(fb.x, fb.y);
                    #pragma unroll
                    for (int m = 0; m < 6; m++) {
                        float4 wv = s_w4[((cs+2*m)*12 + ci)*3 + ky];
                        fma2(acc2[m], x0, pk2(wv.x, wv.x));
                        fma2(acc2[m], x1, pk2(wv.y, wv.y));
                        fma2(acc2[m], x2, pk2(wv.z, wv.z));
                    }
                }
            }
        }
    }
    if (tid < 228) {
        #pragma unroll
        for (int m = 0; m < 6; m++) {
            int c = cg*12 + cs + 2*m;
            float s = bg[c] * rsqrtf(bv[c] + 1e-5f);
            float t = cb[c]*s + bb[c] - bm[c]*s;
            float a0, a1; upk2(a0, a1, acc2[m]);
            float v = fmaxf(fmaxf(fmaf(a0,s,t), fmaf(a1,s,t)), 0.f);
            g_Cb[((b*48+c)*512+h)*114 + wp] = v;
        }
    }
}

// =================== conv3 + bn3 + relu + pool(1,2) ===================
__global__ __launch_bounds__(256) void k_conv3pool(
    const float* __restrict__ w3, const float* __restrict__ cb,
    const float* __restrict__ bg, const float* __restrict__ bb,
    const float* __restrict__ bm, const float* __restrict__ bv)
{
    __shared__ __align__(16) float s_in[12*3*120];
    __shared__ float4 s_w4[12*12*3];
    int tid = threadIdx.x;
    int gid = blockIdx.x;
    int cg = gid & 7; int t = (gid>>3) % 510; int b = gid / (510*8);
    int wp = tid % 57, cs = tid / 57;
    ull acc2[3];
    #pragma unroll
    for (int m = 0; m < 3; m++) acc2[m] = 0ull;

    for (int ch = 0; ch < 4; ch++) {
        int ci0 = ch * 12;
        __syncthreads();
        for (int i = tid; i < 12*3*120; i += 256) {
            int ci = i/360; int r = i%360; int ky = r/120; int wc = r%120;
            int ih = t + ky; int iw = wc - 1;
            float v = 0.f;
            if (iw >= 0 && iw < 114)
                v = g_Cb[((b*48 + ci0+ci)*512 + ih)*114 + iw];
            s_in[(ci*3+ky)*120 + wc] = v;
        }
        {
            float* sw = (float*)s_w4;
            for (int i = tid; i < 12*12*9; i += 256) {
                int cc = i/108; int r = i%108; int ci = r/9; int t9 = r%9;
                int ky = t9/3, kx = t9%3;
                int c = cg*12 + cc;
                sw[((cc*12+ci)*3+ky)*4 + kx] = w3[((c*48 + ci0+ci)*3 + ky)*3 + kx];
            }
        }
        __syncthreads();
        if (tid < 228) {
            #pragma unroll 4
            for (int ci = 0; ci < 12; ci++) {
                #pragma unroll
                for (int ky = 0; ky < 3; ky++) {
                    const float2* row = (const float2*)&s_in[(ci*3+ky)*120 + 2*wp];
                    float2 fa = row[0], fb = row[1];
                    ull x0 = pk2(fa.x, fa.y);
                    ull x1 = pk2(fa.y, fb.x);
                    ull x2 = pk2(fb.x, fb.y);
                    #pragma unroll
                    for (int m = 0; m < 3; m++) {
                        float4 wv = s_w4[((cs+4*m)*12 + ci)*3 + ky];
                        fma2(acc2[m], x0, pk2(wv.x, wv.x));
                        fma2(acc2[m], x1, pk2(wv.y, wv.y));
                        fma2(acc2[m], x2, pk2(wv.z, wv.z));
                    }
                }
            }
        }
    }
    if (tid < 228) {
        #pragma unroll
        for (int m = 0; m < 3; m++) {
            int c = cg*12 + cs + 4*m;
            float s = bg[c] * rsqrtf(bv[c] + 1e-5f);
            float tt = cb[c]*s + bb[c] - bm[c]*s;
            float a0, a1; upk2(a0, a1, acc2[m]);
            float v = fmaxf(fmaxf(fmaf(a0,s,tt), fmaf(a1,s,tt)), 0.f);
            g_D[(b*510+t)*5472 + c*57 + wp] = v;
        }
    }
}

// ============ generic GEMM: C[m][n] = sum_k A[m][k]*B[n][k] + b0[n] (+ b1[n]) ============
// 128x128 tile, BK=8, 256 threads, 8x8 micro-tile, f32x2 accumulators.
__global__ __launch_bounds__(256) void k_gemm(
    const float* __restrict__ A, int lda,
    const float* __restrict__ B, int ldb,
    const float* __restrict__ b0, const float* __restrict__ b1,
    float* __restrict__ C, int ldc, int M, int K)
{
    __shared__ float As[8][128];
    __shared__ float Bs[8][128];
    int tid = threadIdx.x;
    int n0 = blockIdx.x*128, m0 = blockIdx.y*128;
    int lrow = tid >> 1, lk = (tid & 1)*4;
    int msub = (tid >> 4)*8, nsub = (tid & 15)*8;
    ull acc2[8][4];
    #pragma unroll
    for (int m = 0; m < 8; m++)
        #pragma unroll
        for (int np = 0; np < 4; np++) acc2[m][np] = 0ull;

    int nkt = K >> 3;
    for (int kt = 0; kt < nkt; kt++) {
        int k0 = kt*8;
        float4 av = make_float4(0.f,0.f,0.f,0.f);
        int mr = m0 + lrow;
        if (mr < M) av = *(const float4*)&A[(size_t)mr*lda + k0 + lk];
        float4 bv = *(const float4*)&B[(size_t)(n0+lrow)*ldb + k0 + lk];
        __syncthreads();
        As[lk+0][lrow]=av.x; As[lk+1][lrow]=av.y; As[lk+2][lrow]=av.z; As[lk+3][lrow]=av.w;
        Bs[lk+0][lrow]=bv.x; Bs[lk+1][lrow]=bv.y; Bs[lk+2][lrow]=bv.z; Bs[lk+3][lrow]=bv.w;
        __syncthreads();
        #pragma unroll
        for (int k = 0; k < 8; k++) {
            float4 a0 = *(const float4*)&As[k][msub];
            float4 a1 = *(const float4*)&As[k][msub+4];
            ulonglong2 bA = *(const ulonglong2*)&Bs[k][nsub];
            ulonglong2 bB = *(const ulonglong2*)&Bs[k][nsub+4];
            float am[8] = {a0.x,a0.y,a0.z,a0.w,a1.x,a1.y,a1.z,a1.w};
            #pragma unroll
            for (int m = 0; m < 8; m++) {
                ull ap = pk2(am[m], am[m]);
                fma2(acc2[m][0], ap, bA.x);
                fma2(acc2[m][1], ap, bA.y);
                fma2(acc2[m][2], ap, bB.x);
                fma2(acc2[m][3], ap, bB.y);
            }
        }
    }
    float bias[8];
    #pragma unroll
    for (int i = 0; i < 8; i++) {
        int n = n0 + nsub + i;
        bias[i] = b0[n] + (b1 ? b1[n] : 0.f);
    }
    #pragma unroll
    for (int m = 0; m < 8; m++) {
        int row = m0 + msub + m;
        if (row < M) {
            float* cr = &C[(size_t)row*ldc + n0 + nsub];
            #pragma unroll
            for (int np = 0; np < 4; np++) {
                float lo, hi; upk2(lo, hi, acc2[m][np]);
                cr[np*2]   = lo + bias[np*2];
                cr[np*2+1] = hi + bias[np*2+1];
            }
        }
    }
}

// =================== persistent LSTM scan ===================
__device__ __forceinline__ float sigf(float x) { return 1.f/(1.f+expf(-x)); }

// Low-contention grid barrier (leader-only busy poll) — best-measured variant
__device__ __forceinline__ void gbar(unsigned nbar) {
    __threadfence();
    __syncthreads();
    if (threadIdx.x == 0) {
        asm volatile("red.release.gpu.global.add.u32 [%0], %1;"
                     :: "l"(&g_count), "r"(1u) : "memory");
        unsigned tgt = nbar * NCTA;
        unsigned v;
        do {
            asm volatile("ld.acquire.gpu.global.u32 %0, [%1];"
                         : "=r"(v) : "l"(&g_count) : "memory");
        } while (v < tgt);
    }
    __syncthreads();
}

__global__ __launch_bounds__(NTHR, 1) void k_lstm(
    const float* __restrict__ wih0, const float* __restrict__ whh0,
    const float* __restrict__ wih1, const float* __restrict__ whh1,
    const float* __restrict__ bih1, const float* __restrict__ bhh1,
    const float* __restrict__ pw,   const float* __restrict__ pb,
    const float* __restrict__ emb,  float* __restrict__ out)
{
    extern __shared__ __align__(16) ull su[];       // 12288 ull = 98304 B
    float4* xs4 = (float4*)su;
    int tid = threadIdx.x;
    int cta = blockIdx.x;
    int warp = tid >> 5, lane = tid & 31;
    int gw = cta*12 + warp;                          // 0..1535: one task per warp

    const float4* wih04 = (const float4*)wih0;   // rows of 236 float4
    const float4* whh04 = (const float4*)whh0;   // rows of 192 float4
    const float4* wih14 = (const float4*)wih1;   // rows of 192 float4
    const float4* whh14 = (const float4*)whh1;   // rows of 192 float4
    const float4* pw4   = (const float4*)pw;     // rows of 192 float4

    int jt = gw >> 1;                  // hidden unit
    int b0 = (gw & 1) * 8;             // batch half base
    int p0 = (gw & 1) * 4;             // global pair base

    unsigned bt = g_gen;

    // ---- init state (both parity banks) ----
    {
        int i = cta*NTHR + tid;
        if (i < 12288) {
            g_h1[0][i] = 0.f; g_h1[1][i] = 0.f;
            g_h2[0][i] = 0.f; g_h2[1][i] = 0.f;
            g_c1[i] = 0.f;    g_c2[i] = 0.f;
        }
        if (i < 2816) g_prev[i] = 0.f;
    }
    bt++; gbar(bt);

    for (int t = 0; t < 510; t++) {
        int r = t & 1;
        float* h1new = g_h1[1-r];
        float* h2new = g_h2[1-r];

        // ===== phase A: layer-1 gates (K = prev(44) + h1old(192) = 236 fl4; ac part in g_Z) =====
        for (int i = tid; i < 8*236; i += NTHR) {
            int pg = i / 236, c = i - pg*236;
            int ba = 2*pg, bbq = ba+1;
            float4 a0, a1;
            if (c < 44) {
                a0 = __ldcg((const float4*)&g_prev[ba*176] + c);
                a1 = __ldcg((const float4*)&g_prev[bbq*176] + c);
            } else {
                a0 = __ldcg((const float4*)&g_h1[r][ba*768] + (c-44));
                a1 = __ldcg((const float4*)&g_h1[r][bbq*768] + (c-44));
            }
            int base = i*4;
            su[base+0] = pk2(a0.x, a1.x);
            su[base+1] = pk2(a0.y, a1.y);
            su[base+2] = pk2(a0.z, a1.z);
            su[base+3] = pk2(a0.w, a1.w);
        }
        __syncthreads();

        {
            ull acc2[4][4];
            #pragma unroll
            for (int g = 0; g < 4; g++)
                #pragma unroll
                for (int pl = 0; pl < 4; pl++) acc2[g][pl] = 0ull;

            float z4[4];
            if (lane < 8) {
                int m = (b0 + lane)*510 + t;
                #pragma unroll
                for (int g = 0; g < 4; g++)
                    z4[g] = __ldg(&g_Z[m*3072 + g*768 + jt]);
            }

            for (int c = lane; c < 236; c += 32) {
                float4 w0, w1, w2, w3;
                if (c < 44) {
                    int cc = 192 + c;
                    w0 = __ldg(&wih04[(jt       )*236 + cc]);
                    w1 = __ldg(&wih04[(jt +  768)*236 + cc]);
                    w2 = __ldg(&wih04[(jt + 1536)*236 + cc]);
                    w3 = __ldg(&wih04[(jt + 2304)*236 + cc]);
                } else {
                    int cc = c - 44;
                    w0 = __ldg(&whh04[(jt       )*192 + cc]);
                    w1 = __ldg(&whh04[(jt +  768)*192 + cc]);
                    w2 = __ldg(&whh04[(jt + 1536)*192 + cc]);
                    w3 = __ldg(&whh04[(jt + 2304)*192 + cc]);
                }
                ull X[4][4];
                #pragma unroll
                for (int pl = 0; pl < 4; pl++) {
                    int base = ((p0+pl)*236 + c)*4;
                    ulonglong2 xa = *(const ulonglong2*)&su[base];
                    ulonglong2 xb = *(const ulonglong2*)&su[base+2];
                    X[pl][0]=xa.x; X[pl][1]=xa.y; X[pl][2]=xb.x; X[pl][3]=xb.y;
                }
                {
                    ull d0=pk2(w0.x,w0.x), d1=pk2(w0.y,w0.y), d2=pk2(w0.z,w0.z), d3=pk2(w0.w,w0.w);
                    #pragma unroll
                    for (int pl = 0; pl < 4; pl++) {
                        fma2(acc2[0][pl], X[pl][0], d0); fma2(acc2[0][pl], X[pl][1], d1);
                        fma2(acc2[0][pl], X[pl][2], d2); fma2(acc2[0][pl], X[pl][3], d3);
                    }
                }
                {
                    ull d0=pk2(w1.x,w1.x), d1=pk2(w1.y,w1.y), d2=pk2(w1.z,w1.z), d3=pk2(w1.w,w1.w);
                    #pragma unroll
                    for (int pl = 0; pl < 4; pl++) {
                        fma2(acc2[1][pl], X[pl][0], d0); fma2(acc2[1][pl], X[pl][1], d1);
                        fma2(acc2[1][pl], X[pl][2], d2); fma2(acc2[1][pl], X[pl][3], d3);
                    }
                }
                {
                    ull d0=pk2(w2.x,w2.x), d1=pk2(w2.y,w2.y), d2=pk2(w2.z,w2.z), d3=pk2(w2.w,w2.w);
                    #pragma unroll
                    for (int pl = 0; pl < 4; pl++) {
                        fma2(acc2[2][pl], X[pl][0], d0); fma2(acc2[2][pl], X[pl][1], d1);
                        fma2(acc2[2][pl], X[pl][2], d2); fma2(acc2[2][pl], X[pl][3], d3);
                    }
                }
                {
                    ull d0=pk2(w3.x,w3.x), d1=pk2(w3.y,w3.y), d2=pk2(w3.z,w3.z), d3=pk2(w3.w,w3.w);
                    #pragma unroll
                    for (int pl = 0; pl < 4; pl++) {
                        fma2(acc2[3][pl], X[pl][0], d0); fma2(acc2[3][pl], X[pl][1], d1);
                        fma2(acc2[3][pl], X[pl][2], d2); fma2(acc2[3][pl], X[pl][3], d3);
                    }
                }
            }
            #pragma unroll
            for (int off = 16; off; off >>= 1)
                #pragma unroll
                for (int g = 0; g < 4; g++)
                    #pragma unroll
                    for (int pl = 0; pl < 4; pl++) {
                        ull o = __shfl_xor_sync(0xffffffffu, acc2[g][pl], off);
                        add2(acc2[g][pl], o);
                    }
            if (lane < 8) {
                int pl = lane >> 1, hb = lane & 1;
                float zz[4];
                #pragma unroll
                for (int g = 0; g < 4; g++) {
                    float lo, hi; upk2(lo, hi, acc2[g][pl]);
                    zz[g] = (hb ? hi : lo) + z4[g];
                }
                int hi_ = (b0 + lane)*768 + jt;
                float c_ = sigf(zz[1])*g_c1[hi_] + sigf(zz[0])*tanhf(zz[2]);
                g_c1[hi_] = c_;
                h1new[hi_] = sigf(zz[3])*tanhf(c_);
            }
        }
        bt++; gbar(bt);

        // ===== phase B: layer-2 gates (K = h1new(192) + h2old(192) = 384 fl4) =====
        for (int i = tid; i < 8*384; i += NTHR) {
            int pg = i / 384, c = i - pg*384;
            int ba = 2*pg, bbq = ba+1;
            float4 a0, a1;
            if (c < 192) {
                a0 = __ldcg((const float4*)&h1new[ba*768] + c);
                a1 = __ldcg((const float4*)&h1new[bbq*768] + c);
            } else {
                a0 = __ldcg((const float4*)&g_h2[r][ba*768] + (c-192));
                a1 = __ldcg((const float4*)&g_h2[r][bbq*768] + (c-192));
            }
            int base = i*4;
            su[base+0] = pk2(a0.x, a1.x);
            su[base+1] = pk2(a0.y, a1.y);
            su[base+2] = pk2(a0.z, a1.z);
            su[base+3] = pk2(a0.w, a1.w);
        }
        __syncthreads();

        {
            ull acc2[4][4];
            #pragma unroll
            for (int g = 0; g < 4; g++)
                #pragma unroll
                for (int pl = 0; pl < 4; pl++) acc2[g][pl] = 0ull;

            float bsum[4];
            if (lane < 8) {
                #pragma unroll
                for (int g = 0; g < 4; g++)
                    bsum[g] = __ldg(&bih1[jt + g*768]) + __ldg(&bhh1[jt + g*768]);
            }

            for (int c = lane; c < 384; c += 32) {
                float4 w0, w1, w2, w3;
                if (c < 192) {
                    w0 = __ldg(&wih14[(jt       )*192 + c]);
                    w1 = __ldg(&wih14[(jt +  768)*192 + c]);
                    w2 = __ldg(&wih14[(jt + 1536)*192 + c]);
                    w3 = __ldg(&wih14[(jt + 2304)*192 + c]);
                } else {
                    int cc = c - 192;
                    w0 = __ldg(&whh14[(jt       )*192 + cc]);
                    w1 = __ldg(&whh14[(jt +  768)*192 + cc]);
                    w2 = __ldg(&whh14[(jt + 1536)*192 + cc]);
                    w3 = __ldg(&whh14[(jt + 2304)*192 + cc]);
                }
                ull X[4][4];
                #pragma unroll
                for (int pl = 0; pl < 4; pl++) {
                    int base = ((p0+pl)*384 + c)*4;
                    ulonglong2 xa = *(const ulonglong2*)&su[base];
                    ulonglong2 xb = *(const ulonglong2*)&su[base+2];
                    X[pl][0]=xa.x; X[pl][1]=xa.y; X[pl][2]=xb.x; X[pl][3]=xb.y;
                }
                {
                    ull d0=pk2(w0.x,w0.x), d1=pk2(w0.y,w0.y), d2=pk2(w0.z,w0.z), d3=pk2(w0.w,w0.w);
                    #pragma unroll
                    for (int pl = 0; pl < 4; pl++) {
                        fma2(acc2[0][pl], X[pl][0], d0); fma2(acc2[0][pl], X[pl][1], d1);
                        fma2(acc2[0][pl], X[pl][2], d2); fma2(acc2[0][pl], X[pl][3], d3);
                    }
                }
                {
                    ull d0=pk2(w1.x,w1.x), d1=pk2(w1.y,w1.y), d2=pk2(w1.z,w1.z), d3=pk2(w1.w,w1.w);
                    #pragma unroll
                    for (int pl = 0; pl < 4; pl++) {
                        fma2(acc2[1][pl], X[pl][0], d0); fma2(acc2[1][pl], X[pl][1], d1);
                        fma2(acc2[1][pl], X[pl][2], d2); fma2(acc2[1][pl], X[pl][3], d3);
                    }
                }
                {
                    ull d0=pk2(w2.x,w2.x), d1=pk2(w2.y,w2.y), d2=pk2(w2.z,w2.z), d3=pk2(w2.w,w2.w);
                    #pragma unroll
                    for (int pl = 0; pl < 4; pl++) {
                        fma2(acc2[2][pl], X[pl][0], d0); fma2(acc2[2][pl], X[pl][1], d1);
                        fma2(acc2[2][pl], X[pl][2], d2); fma2(acc2[2][pl], X[pl][3], d3);
                    }
                }
                {
                    ull d0=pk2(w3.x,w3.x), d1=pk2(w3.y,w3.y), d2=pk2(w3.z,w3.z), d3=pk2(w3.w,w3.w);
                    #pragma unroll
                    for (int pl = 0; pl < 4; pl++) {
                        fma2(acc2[3][pl], X[pl][0], d0); fma2(acc2[3][pl], X[pl][1], d1);
                        fma2(acc2[3][pl], X[pl][2], d2); fma2(acc2[3][pl], X[pl][3], d3);
                    }
                }
            }
            #pragma unroll
            for (int off = 16; off; off >>= 1)
                #pragma unroll
                for (int g = 0; g < 4; g++)
                    #pragma unroll
                    for (int pl = 0; pl < 4; pl++) {
                        ull o = __shfl_xor_sync(0xffffffffu, acc2[g][pl], off);
                        add2(acc2[g][pl], o);
                    }
            if (lane < 8) {
                int pl = lane >> 1, hb = lane & 1;
                float zz[4];
                #pragma unroll
                for (int g = 0; g < 4; g++) {
                    float lo, hi; upk2(lo, hi, acc2[g][pl]);
                    zz[g] = (hb ? hi : lo) + bsum[g];
                }
                int hi_ = (b0 + lane)*768 + jt;
                float c_ = sigf(zz[1])*g_c2[hi_] + sigf(zz[0])*tanhf(zz[2]);
                g_c2[hi_] = c_;
                h2new[hi_] = sigf(zz[3])*tanhf(c_);
            }
        }
        bt++; gbar(bt);

        // ===== phase C: projection + argmax + embedding feedback (smem-staged) =====
        for (int i = tid; i < 3072; i += NTHR)
            xs4[i] = __ldcg((const float4*)h2new + i);
        __syncthreads();

        if (gw < 1408) {
            int b = gw / 88, p = gw - b*88;
            float a0=0.f, a1=0.f, a2=0.f, a3=0.f, a4=0.f;
            for (int c = lane; c < 192; c += 32) {
                float4 x = xs4[b*192 + c];
                float4 v0 = __ldg(&pw4[(p*5+0)*192 + c]);
                float4 v1 = __ldg(&pw4[(p*5+1)*192 + c]);
                float4 v2 = __ldg(&pw4[(p*5+2)*192 + c]);
                float4 v3 = __ldg(&pw4[(p*5+3)*192 + c]);
                float4 v4 = __ldg(&pw4[(p*5+4)*192 + c]);
                a0 = fmaf(x.x,v0.x, fmaf(x.y,v0.y, fmaf(x.z,v0.z, fmaf(x.w,v0.w, a0))));
                a1 = fmaf(x.x,v1.x, fmaf(x.y,v1.y, fmaf(x.z,v1.z, fmaf(x.w,v1.w, a1))));
                a2 = fmaf(x.x,v2.x, fmaf(x.y,v2.y, fmaf(x.z,v2.z, fmaf(x.w,v2.w, a2))));
                a3 = fmaf(x.x,v3.x, fmaf(x.y,v3.y, fmaf(x.z,v3.z, fmaf(x.w,v3.w, a3))));
                a4 = fmaf(x.x,v4.x, fmaf(x.y,v4.y, fmaf(x.z,v4.z, fmaf(x.w,v4.w, a4))));
            }
            #pragma unroll
            for (int off = 16; off; off >>= 1) {
                a0 += __shfl_xor_sync(0xffffffffu, a0, off);
                a1 += __shfl_xor_sync(0xffffffffu, a1, off);
                a2 += __shfl_xor_sync(0xffffffffu, a2, off);
                a3 += __shfl_xor_sync(0xffffffffu, a3, off);
                a4 += __shfl_xor_sync(0xffffffffu, a4, off);
            }
            if (lane == 0) {
                float l0 = a0 + pb[p*5+0];
                float l1 = a1 + pb[p*5+1];
                float l2 = a2 + pb[p*5+2];
                float l3 = a3 + pb[p*5+3];
                float l4 = a4 + pb[p*5+4];
                float* o = &out[((b*510 + t)*88 + p)*5];
                o[0]=l0; o[1]=l1; o[2]=l2; o[3]=l3; o[4]=l4;
                float best = l0; int bi = 0;
                if (l1 > best) { best = l1; bi = 1; }
                if (l2 > best) { best = l2; bi = 2; }
                if (l3 > best) { best = l3; bi = 3; }
                if (l4 > best) { best = l4; bi = 4; }
                g_prev[b*176 + p*2]     = emb[bi*2];
                g_prev[b*176 + p*2 + 1] = emb[bi*2 + 1];
            }
        }
        bt++; gbar(bt);
    }

    if (cta == 0 && tid == 0) g_gen = bt;
}

// =================== host ===================
extern "C" void kernel_launch(void* const* d_in, const int* in_sizes, int n_in,
                              void* d_out, int out_size)
{
    const float* mel  = (const float*)d_in[0];
    const float* c1w  = (const float*)d_in[1];
    const float* c1b  = (const float*)d_in[2];
    const float* c2w  = (const float*)d_in[3];
    const float* c2b  = (const float*)d_in[4];
    const float* c3w  = (const float*)d_in[5];
    const float* c3b  = (const float*)d_in[6];
    const float* bn1g = (const float*)d_in[7],  *bn1b = (const float*)d_in[8];
    const float* bn1m = (const float*)d_in[9],  *bn1v = (const float*)d_in[10];
    const float* bn2g = (const float*)d_in[11], *bn2b = (const float*)d_in[12];
    const float* bn2m = (const float*)d_in[13], *bn2v = (const float*)d_in[14];
    const float* bn3g = (const float*)d_in[15], *bn3b = (const float*)d_in[16];
    const float* bn3m = (const float*)d_in[17], *bn3v = (const float*)d_in[18];
    const float* fcw  = (const float*)d_in[19], *fcb  = (const float*)d_in[20];
    const float* wih0 = (const float*)d_in[21], *whh0 = (const float*)d_in[22];
    const float* bih0 = (const float*)d_in[23], *bhh0 = (const float*)d_in[24];
    const float* wih1 = (const float*)d_in[25], *whh1 = (const float*)d_in[26];
    const float* bih1 = (const float*)d_in[27], *bhh1 = (const float*)d_in[28];
    const float* pw   = (const float*)d_in[29], *pb   = (const float*)d_in[30];
    const float* emb  = (const float*)d_in[31];
    float* out = (float*)d_out;

    float* d_gD  = nullptr;
    float* d_gac = nullptr;
    float* d_gZ  = nullptr;
    cudaGetSymbolAddress((void**)&d_gD,  g_D);
    cudaGetSymbolAddress((void**)&d_gac, g_ac);
    cudaGetSymbolAddress((void**)&d_gZ,  g_Z);

    cudaFuncSetAttribute((const void*)k_lstm,
                         cudaFuncAttributeMaxDynamicSharedMemorySize, 98304);

    k_conv1<<<(16*512*229 + 255)/256, 256>>>(mel, c1w, c1b, bn1g, bn1b, bn1m, bn1v);
    k_conv2pool<<<16*512*4, 256>>>(c2w, c2b, bn2g, bn2b, bn2m, bn2v);
    k_conv3pool<<<16*510*8, 256>>>(c3w, c3b, bn3g, bn3b, bn3m, bn3v);
    // FC: acoustic = g_D @ fcw^T + fcb   (M=8160, N=768, K=5472)
    k_gemm<<<dim3(6, 64), 256>>>(d_gD, 5472, fcw, 5472, fcb, nullptr,
                                 d_gac, 768, 8160, 5472);
    // Z: g_Z = g_ac @ wih0[:, :768]^T + bih0 + bhh0  (M=8160, N=3072, K=768)
    k_gemm<<<dim3(24, 64), 256>>>(d_gac, 768, wih0, 944, bih0, bhh0,
                                  d_gZ, 3072, 8160, 768);
    k_lstm<<<NCTA, NTHR, 98304>>>(wih0, whh0, wih1, whh1,
                                  bih1, bhh1, pw, pb, emb, out);
}

// round 15
// speedup vs baseline: 1.1985x; 1.1456x over previous
#include <cuda_runtime.h>
#include <math.h>

// ---------------- problem constants ----------------
// B=16, T=512, F=229, C1=48, C3=96, T2=510, HID=768, P=88, NCLS=5
#define NCTA 128
#define NTHR 384

typedef unsigned long long ull;

// ---------------- static device scratch ----------------
__device__ __align__(16) float g_A [90046464];   // conv1 out (16,48,512,229)
__device__ __align__(16) float g_Cb[44826624];   // conv2+pool out (16,48,512,114)
__device__ __align__(16) float g_D [44651520];   // conv3+pool out (8160, 5472)
__device__ __align__(16) float g_ac[ 6266880];   // acoustic (8160, 768)
__device__ __align__(16) float g_Z [25067520];   // ac@wih0[:, :768]^T + biases (8160, 3072)
__device__ __align__(16) float g_h1[2][16*768];
__device__ __align__(16) float g_h2[2][16*768];
__device__ __align__(16) float g_prev[16*176];

// per-group barrier state (persists across launches; monotonic)
__device__ unsigned g_gen;                       // barriers completed (zero-init)
__device__ __align__(128) unsigned g_cnt[2][32]; // per-group arrival counters, padded lines

// ---- f32x2 packed helpers (elementwise .rn — bit-identical per-lane math) ----
__device__ __forceinline__ ull pk2(float lo, float hi) {
    ull r; asm("mov.b64 %0, {%1, %2};" : "=l"(r) : "f"(lo), "f"(hi)); return r;
}
__device__ __forceinline__ void fma2(ull& acc, ull a, ull b) {
    asm("fma.rn.f32x2 %0, %1, %2, %3;" : "=l"(acc) : "l"(a), "l"(b), "l"(acc));
}
__device__ __forceinline__ void add2(ull& acc, ull o) {
    asm("add.rn.f32x2 %0, %1, %2;" : "=l"(acc) : "l"(acc), "l"(o));
}
__device__ __forceinline__ void upk2(float& lo, float& hi, ull v) {
    asm("mov.b64 {%0, %1}, %2;" : "=f"(lo), "=f"(hi) : "l"(v));
}
__device__ __forceinline__ void strel(float* p, float v) {
    asm volatile("st.release.gpu.global.f32 [%0], %1;" :: "l"(p), "f"(v) : "memory");
}
__device__ __forceinline__ void strel2(float* p, float a, float b) {
    asm volatile("st.release.gpu.global.v2.f32 [%0], {%1, %2};"
                 :: "l"(p), "f"(a), "f"(b) : "memory");
}

// =================== conv1 + bn1 + relu ===================
__global__ __launch_bounds__(256) void k_conv1(
    const float* __restrict__ mel, const float* __restrict__ w,
    const float* __restrict__ cb,  const float* __restrict__ bg,
    const float* __restrict__ bb,  const float* __restrict__ bm,
    const float* __restrict__ bv)
{
    __shared__ float sw[48*9];
    __shared__ float sA[48], sB[48];
    int tid = threadIdx.x;
    for (int i = tid; i < 48*9; i += 256) sw[i] = w[i];
    if (tid < 48) {
        float s = bg[tid] * rsqrtf(bv[tid] + 1e-5f);
        sA[tid] = s;
        sB[tid] = cb[tid]*s + bb[tid] - bm[tid]*s;
    }
    __syncthreads();
    int idx = blockIdx.x*256 + tid;
    if (idx >= 16*512*229) return;
    int wq = idx % 229; int h = (idx/229) % 512; int b = idx/(229*512);
    float in[9];
    #pragma unroll
    for (int ky = 0; ky < 3; ky++)
      #pragma unroll
      for (int kx = 0; kx < 3; kx++) {
        int ih = h-1+ky, iw = wq-1+kx;
        in[ky*3+kx] = (ih>=0 && ih<512 && iw>=0 && iw<229)
                      ? mel[(b*512+ih)*229 + iw] : 0.f;
      }
    for (int c = 0; c < 48; c++) {
        float acc = 0.f;
        #pragma unroll
        for (int t9 = 0; t9 < 9; t9++) acc = fmaf(in[t9], sw[c*9+t9], acc);
        float v = fmaf(acc, sA[c], sB[c]);
        g_A[((b*48+c)*512+h)*229 + wq] = v > 0.f ? v : 0.f;
    }
}

// =================== conv2 + bn2 + relu + pool(1,2), 2-row blocked ===================
__global__ __launch_bounds__(256) void k_conv2pool(
    const float* __restrict__ w2, const float* __restrict__ cb,
    const float* __restrict__ bg, const float* __restrict__ bb,
    const float* __restrict__ bm, const float* __restrict__ bv)
{
    __shared__ __align__(16) float s_in[12*4*232];
    __shared__ float4 s_w4[12*12*3];
    int tid = threadIdx.x;
    int gid = blockIdx.x;
    int cg = gid & 3; int hseg = (gid>>2) & 255; int b = gid >> 10;
    int h0 = 2*hseg;
    int wp = tid % 114, cs = tid / 114;
    ull acc2[2][6];
    #pragma unroll
    for (int rr = 0; rr < 2; rr++)
        #pragma unroll
        for (int m = 0; m < 6; m++) acc2[rr][m] = 0ull;

    for (int ch = 0; ch < 4; ch++) {
        int ci0 = ch * 12;
        __syncthreads();
        for (int i = tid; i < 12*4*232; i += 256) {
            int ci = i/928; int r = i%928; int ky = r/232; int wc = r%232;
            int ih = h0-1+ky; int iw = wc-1;
            float v = 0.f;
            if (ih >= 0 && ih < 512 && iw >= 0 && iw < 229)
                v = g_A[((b*48 + ci0+ci)*512 + ih)*229 + iw];
            s_in[(ci*4+ky)*232 + wc] = v;
        }
        {
            float* sw = (float*)s_w4;
            for (int i = tid; i < 12*12*9; i += 256) {
                int cc = i/108; int r = i%108; int ci = r/9; int t9 = r%9;
                int ky = t9/3, kx = t9%3;
                int c = cg*12 + cc;
                sw[((cc*12+ci)*3+ky)*4 + kx] = w2[((c*48 + ci0+ci)*3 + ky)*3 + kx];
            }
        }
        __syncthreads();
        if (tid < 228) {
            #pragma unroll 4
            for (int ci = 0; ci < 12; ci++) {
                #pragma unroll
                for (int ky = 0; ky < 4; ky++) {
                    const float2* row = (const float2*)&s_in[(ci*4+ky)*232 + 2*wp];
                    float2 fa = row[0], fb = row[1];
                    ull x0 = pk2(fa.x, fa.y);
                    ull x1 = pk2(fa.y, fb.x);
                    ull x2 = pk2(fb.x, fb.y);
                    if (ky < 3) {
                        #pragma unroll
                        for (int m = 0; m < 6; m++) {
                            float4 wv = s_w4[((cs+2*m)*12 + ci)*3 + ky];
                            fma2(acc2[0][m], x0, pk2(wv.x, wv.x));
                            fma2(acc2[0][m], x1, pk2(wv.y, wv.y));
                            fma2(acc2[0][m], x2, pk2(wv.z, wv.z));
                        }
                    }
                    if (ky >= 1) {
                        #pragma unroll
                        for (int m = 0; m < 6; m++) {
                            float4 wv = s_w4[((cs+2*m)*12 + ci)*3 + (ky-1)];
                            fma2(acc2[1][m], x0, pk2(wv.x, wv.x));
                            fma2(acc2[1][m], x1, pk2(wv.y, wv.y));
                            fma2(acc2[1][m], x2, pk2(wv.z, wv.z));
                        }
                    }
                }
            }
        }
    }
    if (tid < 228) {
        #pragma unroll
        for (int m = 0; m < 6; m++) {
            int c = cg*12 + cs + 2*m;
            float s = bg[c] * rsqrtf(bv[c] + 1e-5f);
            float t = cb[c]*s + bb[c] - bm[c]*s;
            #pragma unroll
            for (int rr = 0; rr < 2; rr++) {
                float a0, a1; upk2(a0, a1, acc2[rr][m]);
                float v = fmaxf(fmaxf(fmaf(a0,s,t), fmaf(a1,s,t)), 0.f);
                g_Cb[((b*48+c)*512 + h0+rr)*114 + wp] = v;
            }
        }
    }
}

// =================== conv3 + bn3 + relu + pool(1,2), 2-row blocked ===================
__global__ __launch_bounds__(256) void k_conv3pool(
    const float* __restrict__ w3, const float* __restrict__ cb,
    const float* __restrict__ bg, const float* __restrict__ bb,
    const float* __restrict__ bm, const float* __restrict__ bv)
{
    __shared__ __align__(16) float s_in[12*4*120];
    __shared__ float4 s_w4[12*12*3];
    int tid = threadIdx.x;
    int gid = blockIdx.x;
    int cg = gid & 7; int tseg = (gid>>3) % 255; int b = gid / (255*8);
    int t0 = 2*tseg;
    int wp = tid % 57, cs = tid / 57;
    ull acc2[2][3];
    #pragma unroll
    for (int rr = 0; rr < 2; rr++)
        #pragma unroll
        for (int m = 0; m < 3; m++) acc2[rr][m] = 0ull;

    for (int ch = 0; ch < 4; ch++) {
        int ci0 = ch * 12;
        __syncthreads();
        for (int i = tid; i < 12*4*120; i += 256) {
            int ci = i/480; int r = i%480; int ky = r/120; int wc = r%120;
            int ih = t0 + ky; int iw = wc - 1;   // rows t0..t0+3 always valid
            float v = 0.f;
            if (iw >= 0 && iw < 114)
                v = g_Cb[((b*48 + ci0+ci)*512 + ih)*114 + iw];
            s_in[(ci*4+ky)*120 + wc] = v;
        }
        {
            float* sw = (float*)s_w4;
            for (int i = tid; i < 12*12*9; i += 256) {
                int cc = i/108; int r = i%108; int ci = r/9; int t9 = r%9;
                int ky = t9/3, kx = t9%3;
                int c = cg*12 + cc;
                sw[((cc*12+ci)*3+ky)*4 + kx] = w3[((c*48 + ci0+ci)*3 + ky)*3 + kx];
            }
        }
        __syncthreads();
        if (tid < 228) {
            #pragma unroll 4
            for (int ci = 0; ci < 12; ci++) {
                #pragma unroll
                for (int ky = 0; ky < 4; ky++) {
                    const float2* row = (const float2*)&s_in[(ci*4+ky)*120 + 2*wp];
                    float2 fa = row[0], fb = row[1];
                    ull x0 = pk2(fa.x, fa.y);
                    ull x1 = pk2(fa.y, fb.x);
                    ull x2 = pk2(fb.x, fb.y);
                    if (ky < 3) {
                        #pragma unroll
                        for (int m = 0; m < 3; m++) {
                            float4 wv = s_w4[((cs+4*m)*12 + ci)*3 + ky];
                            fma2(acc2[0][m], x0, pk2(wv.x, wv.x));
                            fma2(acc2[0][m], x1, pk2(wv.y, wv.y));
                            fma2(acc2[0][m], x2, pk2(wv.z, wv.z));
                        }
                    }
                    if (ky >= 1) {
                        #pragma unroll
                        for (int m = 0; m < 3; m++) {
                            float4 wv = s_w4[((cs+4*m)*12 + ci)*3 + (ky-1)];
                            fma2(acc2[1][m], x0, pk2(wv.x, wv.x));
                            fma2(acc2[1][m], x1, pk2(wv.y, wv.y));
                            fma2(acc2[1][m], x2, pk2(wv.z, wv.z));
                        }
                    }
                }
            }
        }
    }
    if (tid < 228) {
        #pragma unroll
        for (int m = 0; m < 3; m++) {
            int c = cg*12 + cs + 4*m;
            float s = bg[c] * rsqrtf(bv[c] + 1e-5f);
            float tt = cb[c]*s + bb[c] - bm[c]*s;
            #pragma unroll
            for (int rr = 0; rr < 2; rr++) {
                float a0, a1; upk2(a0, a1, acc2[rr][m]);
                float v = fmaxf(fmaxf(fmaf(a0,s,tt), fmaf(a1,s,tt)), 0.f);
                g_D[(b*510 + t0+rr)*5472 + c*57 + wp] = v;
            }
        }
    }
}

// ============ generic GEMM: C[m][n] = sum_k A[m][k]*B[n][k] + b0[n] (+ b1[n]) ============
__global__ __launch_bounds__(256) void k_gemm(
    const float* __restrict__ A, int lda,
    const float* __restrict__ B, int ldb,
    const float* __restrict__ b0, const float* __restrict__ b1,
    float* __restrict__ C, int ldc, int M, int K)
{
    __shared__ float As[8][128];
    __shared__ float Bs[8][128];
    int tid = threadIdx.x;
    int n0 = blockIdx.x*128, m0 = blockIdx.y*128;
    int lrow = tid >> 1, lk = (tid & 1)*4;
    int msub = (tid >> 4)*8, nsub = (tid & 15)*8;
    ull acc2[8][4];
    #pragma unroll
    for (int m = 0; m < 8; m++)
        #pragma unroll
        for (int np = 0; np < 4; np++) acc2[m][np] = 0ull;

    int nkt = K >> 3;
    for (int kt = 0; kt < nkt; kt++) {
        int k0 = kt*8;
        float4 av = make_float4(0.f,0.f,0.f,0.f);
        int mr = m0 + lrow;
        if (mr < M) av = *(const float4*)&A[(size_t)mr*lda + k0 + lk];
        float4 bv = *(const float4*)&B[(size_t)(n0+lrow)*ldb + k0 + lk];
        __syncthreads();
        As[lk+0][lrow]=av.x; As[lk+1][lrow]=av.y; As[lk+2][lrow]=av.z; As[lk+3][lrow]=av.w;
        Bs[lk+0][lrow]=bv.x; Bs[lk+1][lrow]=bv.y; Bs[lk+2][lrow]=bv.z; Bs[lk+3][lrow]=bv.w;
        __syncthreads();
        #pragma unroll
        for (int k = 0; k < 8; k++) {
            float4 a0 = *(const float4*)&As[k][msub];
            float4 a1 = *(const float4*)&As[k][msub+4];
            ulonglong2 bA = *(const ulonglong2*)&Bs[k][nsub];
            ulonglong2 bB = *(const ulonglong2*)&Bs[k][nsub+4];
            float am[8] = {a0.x,a0.y,a0.z,a0.w,a1.x,a1.y,a1.z,a1.w};
            #pragma unroll
            for (int m = 0; m < 8; m++) {
                ull ap = pk2(am[m], am[m]);
                fma2(acc2[m][0], ap, bA.x);
                fma2(acc2[m][1], ap, bA.y);
                fma2(acc2[m][2], ap, bB.x);
                fma2(acc2[m][3], ap, bB.y);
            }
        }
    }
    float bias[8];
    #pragma unroll
    for (int i = 0; i < 8; i++) {
        int n = n0 + nsub + i;
        bias[i] = b0[n] + (b1 ? b1[n] : 0.f);
    }
    #pragma unroll
    for (int m = 0; m < 8; m++) {
        int row = m0 + msub + m;
        if (row < M) {
            float* cr = &C[(size_t)row*ldc + n0 + nsub];
            #pragma unroll
            for (int np = 0; np < 4; np++) {
                float lo, hi; upk2(lo, hi, acc2[m][np]);
                cr[np*2]   = lo + bias[np*2];
                cr[np*2+1] = hi + bias[np*2+1];
            }
        }
    }
}

// =================== persistent LSTM scan (2 independent groups of 64 CTAs) ===================
__device__ __forceinline__ float sigf(float x) { return 1.f/(1.f+expf(-x)); }

// Per-group barrier: leader red.release arrival + acquire poll. No per-thread fence:
// writers publish their h/prev stores with st.release.gpu.
__device__ __forceinline__ void gbar(int grp, unsigned nbar) {
    __syncthreads();
    if (threadIdx.x == 0) {
        asm volatile("red.release.gpu.global.add.u32 [%0], %1;"
                     :: "l"(&g_cnt[grp][0]), "r"(1u) : "memory");
        unsigned tgt = nbar * 64u;
        unsigned v;
        do {
            asm volatile("ld.acquire.gpu.global.u32 %0, [%1];"
                         : "=r"(v) : "l"(&g_cnt[grp][0]) : "memory");
        } while (v < tgt);
    }
    __syncthreads();
}

__global__ __launch_bounds__(NTHR, 1) void k_lstm(
    const float* __restrict__ wih0, const float* __restrict__ whh0,
    const float* __restrict__ wih1, const float* __restrict__ whh1,
    const float* __restrict__ bih1, const float* __restrict__ bhh1,
    const float* __restrict__ pw,   const float* __restrict__ pb,
    const float* __restrict__ emb,  float* __restrict__ out)
{
    extern __shared__ __align__(16) ull su[];       // 12288 ull = 98304 B
    float4* xs4 = (float4*)su;
    int tid = threadIdx.x;
    int cta = blockIdx.x;
    int grp = cta >> 6;                // 0 or 1: batches grp*8 .. grp*8+7
    int lc  = cta & 63;
    int warp = tid >> 5, lane = tid & 31;
    int jt = lc*12 + warp;             // hidden unit, 0..767 (one per warp)
    int b0 = grp*8;

    const float4* wih04 = (const float4*)wih0;   // rows of 236 float4
    const float4* whh04 = (const float4*)whh0;   // rows of 192 float4
    const float4* wih14 = (const float4*)wih1;   // rows of 192 float4
    const float4* whh14 = (const float4*)whh1;   // rows of 192 float4
    const float4* pw4   = (const float4*)pw;     // rows of 192 float4

    unsigned bt = g_gen;

    // ---- init this group's state (both parity banks) ----
    if (lc < 16) {
        int i = lc*NTHR + tid;         // 0..6143
        int gi = grp*6144 + i;
        g_h1[0][gi] = 0.f; g_h1[1][gi] = 0.f;
        g_h2[0][gi] = 0.f; g_h2[1][gi] = 0.f;
    }
    if (lc < 4) {
        int i = lc*NTHR + tid;
        if (i < 1408) g_prev[grp*1408 + i] = 0.f;
    }
    float creg1 = 0.f, creg2 = 0.f;    // private cell state (lane<8 valid)
    bt++; gbar(grp, bt);

    for (int t = 0; t < 510; t++) {
        int r = t & 1;
        float* h1new = g_h1[1-r];
        float* h2new = g_h2[1-r];

        // ===== phase A: layer-1 gates (K = prev(44) + h1old(192) = 236 fl4; ac part in g_Z) =====
        for (int i = tid; i < 8*236; i += NTHR) {
            int pg = i / 236, c = i - pg*236;
            int ba = b0 + 2*pg, bbq = ba+1;
            float4 a0, a1;
            if (c < 44) {
                a0 = __ldcg((const float4*)&g_prev[ba*176] + c);
                a1 = __ldcg((const float4*)&g_prev[bbq*176] + c);
            } else {
                a0 = __ldcg((const float4*)&g_h1[r][ba*768] + (c-44));
                a1 = __ldcg((const float4*)&g_h1[r][bbq*768] + (c-44));
            }
            int base = i*4;
            su[base+0] = pk2(a0.x, a1.x);
            su[base+1] = pk2(a0.y, a1.y);
            su[base+2] = pk2(a0.z, a1.z);
            su[base+3] = pk2(a0.w, a1.w);
        }
        __syncthreads();

        {
            ull acc2[4][4];
            #pragma unroll
            for (int g = 0; g < 4; g++)
                #pragma unroll
                for (int pl = 0; pl < 4; pl++) acc2[g][pl] = 0ull;

            float z4[4];
            if (lane < 8) {
                int m = (b0 + lane)*510 + t;
                #pragma unroll
                for (int g = 0; g < 4; g++)
                    z4[g] = __ldg(&g_Z[m*3072 + g*768 + jt]);
            }

            for (int c = lane; c < 236; c += 32) {
                float4 w0, w1, w2, w3;
                if (c < 44) {
                    int cc = 192 + c;
                    w0 = __ldg(&wih04[(jt       )*236 + cc]);
                    w1 = __ldg(&wih04[(jt +  768)*236 + cc]);
                    w2 = __ldg(&wih04[(jt + 1536)*236 + cc]);
                    w3 = __ldg(&wih04[(jt + 2304)*236 + cc]);
                } else {
                    int cc = c - 44;
                    w0 = __ldg(&whh04[(jt       )*192 + cc]);
                    w1 = __ldg(&whh04[(jt +  768)*192 + cc]);
                    w2 = __ldg(&whh04[(jt + 1536)*192 + cc]);
                    w3 = __ldg(&whh04[(jt + 2304)*192 + cc]);
                }
                ull X[4][4];
                #pragma unroll
                for (int pl = 0; pl < 4; pl++) {
                    int base = (pl*236 + c)*4;
                    ulonglong2 xa = *(const ulonglong2*)&su[base];
                    ulonglong2 xb = *(const ulonglong2*)&su[base+2];
                    X[pl][0]=xa.x; X[pl][1]=xa.y; X[pl][2]=xb.x; X[pl][3]=xb.y;
                }
                {
                    ull d0=pk2(w0.x,w0.x), d1=pk2(w0.y,w0.y), d2=pk2(w0.z,w0.z), d3=pk2(w0.w,w0.w);
                    #pragma unroll
                    for (int pl = 0; pl < 4; pl++) {
                        fma2(acc2[0][pl], X[pl][0], d0); fma2(acc2[0][pl], X[pl][1], d1);
                        fma2(acc2[0][pl], X[pl][2], d2); fma2(acc2[0][pl], X[pl][3], d3);
                    }
                }
                {
                    ull d0=pk2(w1.x,w1.x), d1=pk2(w1.y,w1.y), d2=pk2(w1.z,w1.z), d3=pk2(w1.w,w1.w);
                    #pragma unroll
                    for (int pl = 0; pl < 4; pl++) {
                        fma2(acc2[1][pl], X[pl][0], d0); fma2(acc2[1][pl], X[pl][1], d1);
                        fma2(acc2[1][pl], X[pl][2], d2); fma2(acc2[1][pl], X[pl][3], d3);
                    }
                }
                {
                    ull d0=pk2(w2.x,w2.x), d1=pk2(w2.y,w2.y), d2=pk2(w2.z,w2.z), d3=pk2(w2.w,w2.w);
                    #pragma unroll
                    for (int pl = 0; pl < 4; pl++) {
                        fma2(acc2[2][pl], X[pl][0], d0); fma2(acc2[2][pl], X[pl][1], d1);
                        fma2(acc2[2][pl], X[pl][2], d2); fma2(acc2[2][pl], X[pl][3], d3);
                    }
                }
                {
                    ull d0=pk2(w3.x,w3.x), d1=pk2(w3.y,w3.y), d2=pk2(w3.z,w3.z), d3=pk2(w3.w,w3.w);
                    #pragma unroll
                    for (int pl = 0; pl < 4; pl++) {
                        fma2(acc2[3][pl], X[pl][0], d0); fma2(acc2[3][pl], X[pl][1], d1);
                        fma2(acc2[3][pl], X[pl][2], d2); fma2(acc2[3][pl], X[pl][3], d3);
                    }
                }
            }
            #pragma unroll
            for (int off = 16; off; off >>= 1)
                #pragma unroll
                for (int g = 0; g < 4; g++)
                    #pragma unroll
                    for (int pl = 0; pl < 4; pl++) {
                        ull o = __shfl_xor_sync(0xffffffffu, acc2[g][pl], off);
                        add2(acc2[g][pl], o);
                    }
            if (lane < 8) {
                int pl = lane >> 1, hb = lane & 1;
                float zz[4];
                #pragma unroll
                for (int g = 0; g < 4; g++) {
                    float lo, hi; upk2(lo, hi, acc2[g][pl]);
                    zz[g] = (hb ? hi : lo) + z4[g];
                }
                float c_ = sigf(zz[1])*creg1 + sigf(zz[0])*tanhf(zz[2]);
                creg1 = c_;
                strel(&h1new[(b0 + lane)*768 + jt], sigf(zz[3])*tanhf(c_));
            }
        }
        bt++; gbar(grp, bt);

        // ===== phase B: layer-2 gates (K = h1new(192) + h2old(192) = 384 fl4) =====
        for (int i = tid; i < 8*384; i += NTHR) {
            int pg = i / 384, c = i - pg*384;
            int ba = b0 + 2*pg, bbq = ba+1;
            float4 a0, a1;
            if (c < 192) {
                a0 = __ldcg((const float4*)&h1new[ba*768] + c);
                a1 = __ldcg((const float4*)&h1new[bbq*768] + c);
            } else {
                a0 = __ldcg((const float4*)&g_h2[r][ba*768] + (c-192));
                a1 = __ldcg((const float4*)&g_h2[r][bbq*768] + (c-192));
            }
            int base = i*4;
            su[base+0] = pk2(a0.x, a1.x);
            su[base+1] = pk2(a0.y, a1.y);
            su[base+2] = pk2(a0.z, a1.z);
            su[base+3] = pk2(a0.w, a1.w);
        }
        __syncthreads();

        {
            ull acc2[4][4];
            #pragma unroll
            for (int g = 0; g < 4; g++)
                #pragma unroll
                for (int pl = 0; pl < 4; pl++) acc2[g][pl] = 0ull;

            float bsum[4];
            if (lane < 8) {
                #pragma unroll
                for (int g = 0; g < 4; g++)
                    bsum[g] = __ldg(&bih1[jt + g*768]) + __ldg(&bhh1[jt + g*768]);
            }

            for (int c = lane; c < 384; c += 32) {
                float4 w0, w1, w2, w3;
                if (c < 192) {
                    w0 = __ldg(&wih14[(jt       )*192 + c]);
                    w1 = __ldg(&wih14[(jt +  768)*192 + c]);
                    w2 = __ldg(&wih14[(jt + 1536)*192 + c]);
                    w3 = __ldg(&wih14[(jt + 2304)*192 + c]);
                } else {
                    int cc = c - 192;
                    w0 = __ldg(&whh14[(jt       )*192 + cc]);
                    w1 = __ldg(&whh14[(jt +  768)*192 + cc]);
                    w2 = __ldg(&whh14[(jt + 1536)*192 + cc]);
                    w3 = __ldg(&whh14[(jt + 2304)*192 + cc]);
                }
                ull X[4][4];
                #pragma unroll
                for (int pl = 0; pl < 4; pl++) {
                    int base = (pl*384 + c)*4;
                    ulonglong2 xa = *(const ulonglong2*)&su[base];
                    ulonglong2 xb = *(const ulonglong2*)&su[base+2];
                    X[pl][0]=xa.x; X[pl][1]=xa.y; X[pl][2]=xb.x; X[pl][3]=xb.y;
                }
                {
                    ull d0=pk2(w0.x,w0.x), d1=pk2(w0.y,w0.y), d2=pk2(w0.z,w0.z), d3=pk2(w0.w,w0.w);
                    #pragma unroll
                    for (int pl = 0; pl < 4; pl++) {
                        fma2(acc2[0][pl], X[pl][0], d0); fma2(acc2[0][pl], X[pl][1], d1);
                        fma2(acc2[0][pl], X[pl][2], d2); fma2(acc2[0][pl], X[pl][3], d3);
                    }
                }
                {
                    ull d0=pk2(w1.x,w1.x), d1=pk2(w1.y,w1.y), d2=pk2(w1.z,w1.z), d3=pk2(w1.w,w1.w);
                    #pragma unroll
                    for (int pl = 0; pl < 4; pl++) {
                        fma2(acc2[1][pl], X[pl][0], d0); fma2(acc2[1][pl], X[pl][1], d1);
                        fma2(acc2[1][pl], X[pl][2], d2); fma2(acc2[1][pl], X[pl][3], d3);
                    }
                }
                {
                    ull d0=pk2(w2.x,w2.x), d1=pk2(w2.y,w2.y), d2=pk2(w2.z,w2.z), d3=pk2(w2.w,w2.w);
                    #pragma unroll
                    for (int pl = 0; pl < 4; pl++) {
                        fma2(acc2[2][pl], X[pl][0], d0); fma2(acc2[2][pl], X[pl][1], d1);
                        fma2(acc2[2][pl], X[pl][2], d2); fma2(acc2[2][pl], X[pl][3], d3);
                    }
                }
                {
                    ull d0=pk2(w3.x,w3.x), d1=pk2(w3.y,w3.y), d2=pk2(w3.z,w3.z), d3=pk2(w3.w,w3.w);
                    #pragma unroll
                    for (int pl = 0; pl < 4; pl++) {
                        fma2(acc2[3][pl], X[pl][0], d0); fma2(acc2[3][pl], X[pl][1], d1);
                        fma2(acc2[3][pl], X[pl][2], d2); fma2(acc2[3][pl], X[pl][3], d3);
                    }
                }
            }
            #pragma unroll
            for (int off = 16; off; off >>= 1)
                #pragma unroll
                for (int g = 0; g < 4; g++)
                    #pragma unroll
                    for (int pl = 0; pl < 4; pl++) {
                        ull o = __shfl_xor_sync(0xffffffffu, acc2[g][pl], off);
                        add2(acc2[g][pl], o);
                    }
            if (lane < 8) {
                int pl = lane >> 1, hb = lane & 1;
                float zz[4];
                #pragma unroll
                for (int g = 0; g < 4; g++) {
                    float lo, hi; upk2(lo, hi, acc2[g][pl]);
                    zz[g] = (hb ? hi : lo) + bsum[g];
                }
                float c_ = sigf(zz[1])*creg2 + sigf(zz[0])*tanhf(zz[2]);
                creg2 = c_;
                strel(&h2new[(b0 + lane)*768 + jt], sigf(zz[3])*tanhf(c_));
            }
        }
        bt++; gbar(grp, bt);

        // ===== phase C: projection + argmax + embedding feedback (group's 8 batches) =====
        for (int i = tid; i < 1536; i += NTHR)
            xs4[i] = __ldcg((const float4*)&h2new[b0*768] + i);
        __syncthreads();

        {
            int gwl = lc*12 + warp;            // 0..767
            if (gwl < 704) {
                int bl = gwl / 88, p = gwl - bl*88;
                int b = b0 + bl;
                float a0=0.f, a1=0.f, a2=0.f, a3=0.f, a4=0.f;
                for (int c = lane; c < 192; c += 32) {
                    float4 x = xs4[bl*192 + c];
                    float4 v0 = __ldg(&pw4[(p*5+0)*192 + c]);
                    float4 v1 = __ldg(&pw4[(p*5+1)*192 + c]);
                    float4 v2 = __ldg(&pw4[(p*5+2)*192 + c]);
                    float4 v3 = __ldg(&pw4[(p*5+3)*192 + c]);
                    float4 v4 = __ldg(&pw4[(p*5+4)*192 + c]);
                    a0 = fmaf(x.x,v0.x, fmaf(x.y,v0.y, fmaf(x.z,v0.z, fmaf(x.w,v0.w, a0))));
                    a1 = fmaf(x.x,v1.x, fmaf(x.y,v1.y, fmaf(x.z,v1.z, fmaf(x.w,v1.w, a1))));
                    a2 = fmaf(x.x,v2.x, fmaf(x.y,v2.y, fmaf(x.z,v2.z, fmaf(x.w,v2.w, a2))));
                    a3 = fmaf(x.x,v3.x, fmaf(x.y,v3.y, fmaf(x.z,v3.z, fmaf(x.w,v3.w, a3))));
                    a4 = fmaf(x.x,v4.x, fmaf(x.y,v4.y, fmaf(x.z,v4.z, fmaf(x.w,v4.w, a4))));
                }
                #pragma unroll
                for (int off = 16; off; off >>= 1) {
                    a0 += __shfl_xor_sync(0xffffffffu, a0, off);
                    a1 += __shfl_xor_sync(0xffffffffu, a1, off);
                    a2 += __shfl_xor_sync(0xffffffffu, a2, off);
                    a3 += __shfl_xor_sync(0xffffffffu, a3, off);
                    a4 += __shfl_xor_sync(0xffffffffu, a4, off);
                }
                if (lane == 0) {
                    float l0 = a0 + pb[p*5+0];
                    float l1 = a1 + pb[p*5+1];
                    float l2 = a2 + pb[p*5+2];
                    float l3 = a3 + pb[p*5+3];
                    float l4 = a4 + pb[p*5+4];
                    float* o = &out[((b*510 + t)*88 + p)*5];
                    o[0]=l0; o[1]=l1; o[2]=l2; o[3]=l3; o[4]=l4;
                    float best = l0; int bi = 0;
                    if (l1 > best) { best = l1; bi = 1; }
                    if (l2 > best) { best = l2; bi = 2; }
                    if (l3 > best) { best = l3; bi = 3; }
                    if (l4 > best) { best = l4; bi = 4; }
                    strel2(&g_prev[b*176 + p*2], emb[bi*2], emb[bi*2 + 1]);
                }
            }
        }
        bt++; gbar(grp, bt);
    }

    if (cta == 0 && tid == 0) g_gen = bt;
}

// =================== host ===================
extern "C" void kernel_launch(void* const* d_in, const int* in_sizes, int n_in,
                              void* d_out, int out_size)
{
    const float* mel  = (const float*)d_in[0];
    const float* c1w  = (const float*)d_in[1];
    const float* c1b  = (const float*)d_in[2];
    const float* c2w  = (const float*)d_in[3];
    const float* c2b  = (const float*)d_in[4];
    const float* c3w  = (const float*)d_in[5];
    const float* c3b  = (const float*)d_in[6];
    const float* bn1g = (const float*)d_in[7],  *bn1b = (const float*)d_in[8];
    const float* bn1m = (const float*)d_in[9],  *bn1v = (const float*)d_in[10];
    const float* bn2g = (const float*)d_in[11], *bn2b = (const float*)d_in[12];
    const float* bn2m = (const float*)d_in[13], *bn2v = (const float*)d_in[14];
    const float* bn3g = (const float*)d_in[15], *bn3b = (const float*)d_in[16];
    const float* bn3m = (const float*)d_in[17], *bn3v = (const float*)d_in[18];
    const float* fcw  = (const float*)d_in[19], *fcb  = (const float*)d_in[20];
    const float* wih0 = (const float*)d_in[21], *whh0 = (const float*)d_in[22];
    const float* bih0 = (const float*)d_in[23], *bhh0 = (const float*)d_in[24];
    const float* wih1 = (const float*)d_in[25], *whh1 = (const float*)d_in[26];
    const float* bih1 = (const float*)d_in[27], *bhh1 = (const float*)d_in[28];
    const float* pw   = (const float*)d_in[29], *pb   = (const float*)d_in[30];
    const float* emb  = (const float*)d_in[31];
    float* out = (float*)d_out;

    float* d_gD  = nullptr;
    float* d_gac = nullptr;
    float* d_gZ  = nullptr;
    cudaGetSymbolAddress((void**)&d_gD,  g_D);
    cudaGetSymbolAddress((void**)&d_gac, g_ac);
    cudaGetSymbolAddress((void**)&d_gZ,  g_Z);

    cudaFuncSetAttribute((const void*)k_lstm,
                         cudaFuncAttributeMaxDynamicSharedMemorySize, 98304);

    k_conv1<<<(16*512*229 + 255)/256, 256>>>(mel, c1w, c1b, bn1g, bn1b, bn1m, bn1v);
    k_conv2pool<<<16*256*4, 256>>>(c2w, c2b, bn2g, bn2b, bn2m, bn2v);
    k_conv3pool<<<16*255*8, 256>>>(c3w, c3b, bn3g, bn3b, bn3m, bn3v);
    // FC: acoustic = g_D @ fcw^T + fcb   (M=8160, N=768, K=5472)
    k_gemm<<<dim3(6, 64), 256>>>(d_gD, 5472, fcw, 5472, fcb, nullptr,
                                 d_gac, 768, 8160, 5472);
    // Z: g_Z = g_ac @ wih0[:, :768]^T + bih0 + bhh0  (M=8160, N=3072, K=768)
    k_gemm<<<dim3(24, 64), 256>>>(d_gac, 768, wih0, 944, bih0, bhh0,
                                  d_gZ, 3072, 8160, 768);
    k_lstm<<<NCTA, NTHR, 98304>>>(wih0, whh0, wih1, whh1,
                                  bih1, bhh1, pw, pb, emb, out);
}

// round 16
// speedup vs baseline: 1.2130x; 1.0120x over previous
#include <cuda_runtime.h>
#include <math.h>

// ---------------- problem constants ----------------
// B=16, T=512, F=229, C1=48, C3=96, T2=510, HID=768, P=88, NCLS=5
#define NCTA 128
#define NTHR 384

typedef unsigned long long ull;

// ---------------- static device scratch ----------------
__device__ __align__(16) float g_A [90046464];   // conv1 out (16,48,512,229)
__device__ __align__(16) float g_Cb[44826624];   // conv2+pool out (16,48,512,114)
__device__ __align__(16) float g_D [44651520];   // conv3+pool out (8160, 5472)
__device__ __align__(16) float g_ac[ 6266880];   // acoustic (8160, 768)
__device__ __align__(16) float g_Z [25067520];   // ac@wih0[:, :768]^T + biases (8160, 3072)
__device__ __align__(16) float g_W1p[2899968];   // packed L1 gate weights: [j][g][236 fl4]
__device__ __align__(16) float g_W2p[4718592];   // packed L2 gate weights: [j][g][384 fl4]
__device__ __align__(16) float g_h1[2][16*768];
__device__ __align__(16) float g_h2[2][16*768];
__device__ __align__(16) float g_prev[16*176];

// per-group barrier state (persists across launches; monotonic)
__device__ unsigned g_gen;                       // barriers completed (zero-init)
__device__ __align__(128) unsigned g_cnt[2][32]; // per-group arrival counters, padded lines

// ---- f32x2 packed helpers (elementwise .rn — bit-identical per-lane math) ----
__device__ __forceinline__ ull pk2(float lo, float hi) {
    ull r; asm("mov.b64 %0, {%1, %2};" : "=l"(r) : "f"(lo), "f"(hi)); return r;
}
__device__ __forceinline__ void fma2(ull& acc, ull a, ull b) {
    asm("fma.rn.f32x2 %0, %1, %2, %3;" : "=l"(acc) : "l"(a), "l"(b), "l"(acc));
}
__device__ __forceinline__ void add2(ull& acc, ull o) {
    asm("add.rn.f32x2 %0, %1, %2;" : "=l"(acc) : "l"(acc), "l"(o));
}
__device__ __forceinline__ void upk2(float& lo, float& hi, ull v) {
    asm("mov.b64 {%0, %1}, %2;" : "=f"(lo), "=f"(hi) : "l"(v));
}
__device__ __forceinline__ void strel(float* p, float v) {
    asm volatile("st.release.gpu.global.f32 [%0], %1;" :: "l"(p), "f"(v) : "memory");
}
__device__ __forceinline__ void strel2(float* p, float a, float b) {
    asm volatile("st.release.gpu.global.v2.f32 [%0], {%1, %2};"
                 :: "l"(p), "f"(a), "f"(b) : "memory");
}

// ====== weight repack: per-j contiguous gate rows in x-order ======
// W1p[j][g][c] (c in fl4): c<44 -> wih0 row (g*768+j) fl4 192+c ; else whh0 row fl4 (c-44)
__global__ void k_pack1(const float* __restrict__ wih0, const float* __restrict__ whh0) {
    int i = blockIdx.x*256 + threadIdx.x;          // fl4 index, 768*944
    if (i >= 768*944) return;
    int j = i / 944, rem = i % 944;
    int g = rem / 236, c = rem % 236;
    int gj = g*768 + j;
    float4 v;
    if (c < 44) v = *((const float4*)wih0 + (size_t)gj*236 + 192 + c);
    else        v = *((const float4*)whh0 + (size_t)gj*192 + (c-44));
    *((float4*)g_W1p + i) = v;
}
// W2p[j][g][c]: c<192 -> wih1 fl4 c ; else whh1 fl4 (c-192)
__global__ void k_pack2(const float* __restrict__ wih1, const float* __restrict__ whh1) {
    int i = blockIdx.x*256 + threadIdx.x;          // 768*1536
    if (i >= 768*1536) return;
    int j = i / 1536, rem = i % 1536;
    int g = rem / 384, c = rem % 384;
    int gj = g*768 + j;
    float4 v;
    if (c < 192) v = *((const float4*)wih1 + (size_t)gj*192 + c);
    else         v = *((const float4*)whh1 + (size_t)gj*192 + (c-192));
    *((float4*)g_W2p + i) = v;
}

// =================== conv1 + bn1 + relu ===================
__global__ __launch_bounds__(256) void k_conv1(
    const float* __restrict__ mel, const float* __restrict__ w,
    const float* __restrict__ cb,  const float* __restrict__ bg,
    const float* __restrict__ bb,  const float* __restrict__ bm,
    const float* __restrict__ bv)
{
    __shared__ float sw[48*9];
    __shared__ float sA[48], sB[48];
    int tid = threadIdx.x;
    for (int i = tid; i < 48*9; i += 256) sw[i] = w[i];
    if (tid < 48) {
        float s = bg[tid] * rsqrtf(bv[tid] + 1e-5f);
        sA[tid] = s;
        sB[tid] = cb[tid]*s + bb[tid] - bm[tid]*s;
    }
    __syncthreads();
    int idx = blockIdx.x*256 + tid;
    if (idx >= 16*512*229) return;
    int wq = idx % 229; int h = (idx/229) % 512; int b = idx/(229*512);
    float in[9];
    #pragma unroll
    for (int ky = 0; ky < 3; ky++)
      #pragma unroll
      for (int kx = 0; kx < 3; kx++) {
        int ih = h-1+ky, iw = wq-1+kx;
        in[ky*3+kx] = (ih>=0 && ih<512 && iw>=0 && iw<229)
                      ? mel[(b*512+ih)*229 + iw] : 0.f;
      }
    for (int c = 0; c < 48; c++) {
        float acc = 0.f;
        #pragma unroll
        for (int t9 = 0; t9 < 9; t9++) acc = fmaf(in[t9], sw[c*9+t9], acc);
        float v = fmaf(acc, sA[c], sB[c]);
        g_A[((b*48+c)*512+h)*229 + wq] = v > 0.f ? v : 0.f;
    }
}

// =================== conv2 + bn2 + relu + pool(1,2), 2-row blocked ===================
__global__ __launch_bounds__(256) void k_conv2pool(
    const float* __restrict__ w2, const float* __restrict__ cb,
    const float* __restrict__ bg, const float* __restrict__ bb,
    const float* __restrict__ bm, const float* __restrict__ bv)
{
    __shared__ __align__(16) float s_in[12*4*232];
    __shared__ float4 s_w4[12*12*3];
    int tid = threadIdx.x;
    int gid = blockIdx.x;
    int cg = gid & 3; int hseg = (gid>>2) & 255; int b = gid >> 10;
    int h0 = 2*hseg;
    int wp = tid % 114, cs = tid / 114;
    ull acc2[2][6];
    #pragma unroll
    for (int rr = 0; rr < 2; rr++)
        #pragma unroll
        for (int m = 0; m < 6; m++) acc2[rr][m] = 0ull;

    for (int ch = 0; ch < 4; ch++) {
        int ci0 = ch * 12;
        __syncthreads();
        for (int i = tid; i < 12*4*232; i += 256) {
            int ci = i/928; int r = i%928; int ky = r/232; int wc = r%232;
            int ih = h0-1+ky; int iw = wc-1;
            float v = 0.f;
            if (ih >= 0 && ih < 512 && iw >= 0 && iw < 229)
                v = g_A[((b*48 + ci0+ci)*512 + ih)*229 + iw];
            s_in[(ci*4+ky)*232 + wc] = v;
        }
        {
            float* sw = (float*)s_w4;
            for (int i = tid; i < 12*12*9; i += 256) {
                int cc = i/108; int r = i%108; int ci = r/9; int t9 = r%9;
                int ky = t9/3, kx = t9%3;
                int c = cg*12 + cc;
                sw[((cc*12+ci)*3+ky)*4 + kx] = w2[((c*48 + ci0+ci)*3 + ky)*3 + kx];
            }
        }
        __syncthreads();
        if (tid < 228) {
            #pragma unroll 4
            for (int ci = 0; ci < 12; ci++) {
                #pragma unroll
                for (int ky = 0; ky < 4; ky++) {
                    const float2* row = (const float2*)&s_in[(ci*4+ky)*232 + 2*wp];
                    float2 fa = row[0], fb = row[1];
                    ull x0 = pk2(fa.x, fa.y);
                    ull x1 = pk2(fa.y, fb.x);
                    ull x2 = pk2(fb.x, fb.y);
                    if (ky < 3) {
                        #pragma unroll
                        for (int m = 0; m < 6; m++) {
                            float4 wv = s_w4[((cs+2*m)*12 + ci)*3 + ky];
                            fma2(acc2[0][m], x0, pk2(wv.x, wv.x));
                            fma2(acc2[0][m], x1, pk2(wv.y, wv.y));
                            fma2(acc2[0][m], x2, pk2(wv.z, wv.z));
                        }
                    }
                    if (ky >= 1) {
                        #pragma unroll
                        for (int m = 0; m < 6; m++) {
                            float4 wv = s_w4[((cs+2*m)*12 + ci)*3 + (ky-1)];
                            fma2(acc2[1][m], x0, pk2(wv.x, wv.x));
                            fma2(acc2[1][m], x1, pk2(wv.y, wv.y));
                            fma2(acc2[1][m], x2, pk2(wv.z, wv.z));
                        }
                    }
                }
            }
        }
    }
    if (tid < 228) {
        #pragma unroll
        for (int m = 0; m < 6; m++) {
            int c = cg*12 + cs + 2*m;
            float s = bg[c] * rsqrtf(bv[c] + 1e-5f);
            float t = cb[c]*s + bb[c] - bm[c]*s;
            #pragma unroll
            for (int rr = 0; rr < 2; rr++) {
                float a0, a1; upk2(a0, a1, acc2[rr][m]);
                float v = fmaxf(fmaxf(fmaf(a0,s,t), fmaf(a1,s,t)), 0.f);
                g_Cb[((b*48+c)*512 + h0+rr)*114 + wp] = v;
            }
        }
    }
}

// =================== conv3 + bn3 + relu + pool(1,2), 2-row blocked ===================
__global__ __launch_bounds__(256) void k_conv3pool(
    const float* __restrict__ w3, const float* __restrict__ cb,
    const float* __restrict__ bg, const float* __restrict__ bb,
    const float* __restrict__ bm, const float* __restrict__ bv)
{
    __shared__ __align__(16) float s_in[12*4*120];
    __shared__ float4 s_w4[12*12*3];
    int tid = threadIdx.x;
    int gid = blockIdx.x;
    int cg = gid & 7; int tseg = (gid>>3) % 255; int b = gid / (255*8);
    int t0 = 2*tseg;
    int wp = tid % 57, cs = tid / 57;
    ull acc2[2][3];
    #pragma unroll
    for (int rr = 0; rr < 2; rr++)
        #pragma unroll
        for (int m = 0; m < 3; m++) acc2[rr][m] = 0ull;

    for (int ch = 0; ch < 4; ch++) {
        int ci0 = ch * 12;
        __syncthreads();
        for (int i = tid; i < 12*4*120; i += 256) {
            int ci = i/480; int r = i%480; int ky = r/120; int wc = r%120;
            int ih = t0 + ky; int iw = wc - 1;
            float v = 0.f;
            if (iw >= 0 && iw < 114)
                v = g_Cb[((b*48 + ci0+ci)*512 + ih)*114 + iw];
            s_in[(ci*4+ky)*120 + wc] = v;
        }
        {
            float* sw = (float*)s_w4;
            for (int i = tid; i < 12*12*9; i += 256) {
                int cc = i/108; int r = i%108; int ci = r/9; int t9 = r%9;
                int ky = t9/3, kx = t9%3;
                int c = cg*12 + cc;
                sw[((cc*12+ci)*3+ky)*4 + kx] = w3[((c*48 + ci0+ci)*3 + ky)*3 + kx];
            }
        }
        __syncthreads();
        if (tid < 228) {
            #pragma unroll 4
            for (int ci = 0; ci < 12; ci++) {
                #pragma unroll
                for (int ky = 0; ky < 4; ky++) {
                    const float2* row = (const float2*)&s_in[(ci*4+ky)*120 + 2*wp];
                    float2 fa = row[0], fb = row[1];
                    ull x0 = pk2(fa.x, fa.y);
                    ull x1 = pk2(fa.y, fb.x);
                    ull x2 = pk2(fb.x, fb.y);
                    if (ky < 3) {
                        #pragma unroll
                        for (int m = 0; m < 3; m++) {
                            float4 wv = s_w4[((cs+4*m)*12 + ci)*3 + ky];
                            fma2(acc2[0][m], x0, pk2(wv.x, wv.x));
                            fma2(acc2[0][m], x1, pk2(wv.y, wv.y));
                            fma2(acc2[0][m], x2, pk2(wv.z, wv.z));
                        }
                    }
                    if (ky >= 1) {
                        #pragma unroll
                        for (int m = 0; m < 3; m++) {
                            float4 wv = s_w4[((cs+4*m)*12 + ci)*3 + (ky-1)];
                            fma2(acc2[1][m], x0, pk2(wv.x, wv.x));
                            fma2(acc2[1][m], x1, pk2(wv.y, wv.y));
                            fma2(acc2[1][m], x2, pk2(wv.z, wv.z));
                        }
                    }
                }
            }
        }
    }
    if (tid < 228) {
        #pragma unroll
        for (int m = 0; m < 3; m++) {
            int c = cg*12 + cs + 4*m;
            float s = bg[c] * rsqrtf(bv[c] + 1e-5f);
            float tt = cb[c]*s + bb[c] - bm[c]*s;
            #pragma unroll
            for (int rr = 0; rr < 2; rr++) {
                float a0, a1; upk2(a0, a1, acc2[rr][m]);
                float v = fmaxf(fmaxf(fmaf(a0,s,tt), fmaf(a1,s,tt)), 0.f);
                g_D[(b*510 + t0+rr)*5472 + c*57 + wp] = v;
            }
        }
    }
}

// ============ generic GEMM: C[m][n] = sum_k A[m][k]*B[n][k] + b0[n] (+ b1[n]) ============
__global__ __launch_bounds__(256) void k_gemm(
    const float* __restrict__ A, int lda,
    const float* __restrict__ B, int ldb,
    const float* __restrict__ b0, const float* __restrict__ b1,
    float* __restrict__ C, int ldc, int M, int K)
{
    __shared__ float As[8][128];
    __shared__ float Bs[8][128];
    int tid = threadIdx.x;
    int n0 = blockIdx.x*128, m0 = blockIdx.y*128;
    int lrow = tid >> 1, lk = (tid & 1)*4;
    int msub = (tid >> 4)*8, nsub = (tid & 15)*8;
    ull acc2[8][4];
    #pragma unroll
    for (int m = 0; m < 8; m++)
        #pragma unroll
        for (int np = 0; np < 4; np++) acc2[m][np] = 0ull;

    int nkt = K >> 3;
    for (int kt = 0; kt < nkt; kt++) {
        int k0 = kt*8;
        float4 av = make_float4(0.f,0.f,0.f,0.f);
        int mr = m0 + lrow;
        if (mr < M) av = *(const float4*)&A[(size_t)mr*lda + k0 + lk];
        float4 bv = *(const float4*)&B[(size_t)(n0+lrow)*ldb + k0 + lk];
        __syncthreads();
        As[lk+0][lrow]=av.x; As[lk+1][lrow]=av.y; As[lk+2][lrow]=av.z; As[lk+3][lrow]=av.w;
        Bs[lk+0][lrow]=bv.x; Bs[lk+1][lrow]=bv.y; Bs[lk+2][lrow]=bv.z; Bs[lk+3][lrow]=bv.w;
        __syncthreads();
        #pragma unroll
        for (int k = 0; k < 8; k++) {
            float4 a0 = *(const float4*)&As[k][msub];
            float4 a1 = *(const float4*)&As[k][msub+4];
            ulonglong2 bA = *(const ulonglong2*)&Bs[k][nsub];
            ulonglong2 bB = *(const ulonglong2*)&Bs[k][nsub+4];
            float am[8] = {a0.x,a0.y,a0.z,a0.w,a1.x,a1.y,a1.z,a1.w};
            #pragma unroll
            for (int m = 0; m < 8; m++) {
                ull ap = pk2(am[m], am[m]);
                fma2(acc2[m][0], ap, bA.x);
                fma2(acc2[m][1], ap, bA.y);
                fma2(acc2[m][2], ap, bB.x);
                fma2(acc2[m][3], ap, bB.y);
            }
        }
    }
    float bias[8];
    #pragma unroll
    for (int i = 0; i < 8; i++) {
        int n = n0 + nsub + i;
        bias[i] = b0[n] + (b1 ? b1[n] : 0.f);
    }
    #pragma unroll
    for (int m = 0; m < 8; m++) {
        int row = m0 + msub + m;
        if (row < M) {
            float* cr = &C[(size_t)row*ldc + n0 + nsub];
            #pragma unroll
            for (int np = 0; np < 4; np++) {
                float lo, hi; upk2(lo, hi, acc2[m][np]);
                cr[np*2]   = lo + bias[np*2];
                cr[np*2+1] = hi + bias[np*2+1];
            }
        }
    }
}

// =================== persistent LSTM scan (2 independent groups of 64 CTAs) ===================
__device__ __forceinline__ float sigf(float x) { return 1.f/(1.f+expf(-x)); }

__device__ __forceinline__ void gbar(int grp, unsigned nbar) {
    __syncthreads();
    if (threadIdx.x == 0) {
        asm volatile("red.release.gpu.global.add.u32 [%0], %1;"
                     :: "l"(&g_cnt[grp][0]), "r"(1u) : "memory");
        unsigned tgt = nbar * 64u;
        unsigned v;
        do {
            asm volatile("ld.acquire.gpu.global.u32 %0, [%1];"
                         : "=r"(v) : "l"(&g_cnt[grp][0]) : "memory");
        } while (v < tgt);
    }
    __syncthreads();
}

__global__ __launch_bounds__(NTHR, 1) void k_lstm(
    const float* __restrict__ bih1, const float* __restrict__ bhh1,
    const float* __restrict__ pw,   const float* __restrict__ pb,
    const float* __restrict__ emb,  float* __restrict__ out)
{
    extern __shared__ __align__(16) ull su[];       // 12288 ull = 98304 B
    float4* xs4 = (float4*)su;
    int tid = threadIdx.x;
    int cta = blockIdx.x;
    int grp = cta >> 6;                // 0 or 1: batches grp*8 .. grp*8+7
    int lc  = cta & 63;
    int warp = tid >> 5, lane = tid & 31;
    int jt = lc*12 + warp;             // hidden unit, 0..767 (one per warp)
    int b0 = grp*8;

    const float4* pw4 = (const float4*)pw;     // rows of 192 float4
    const float4* wr1 = (const float4*)g_W1p + (size_t)jt*944;   // 4 x 236
    const float4* wr2 = (const float4*)g_W2p + (size_t)jt*1536;  // 4 x 384

    unsigned bt = g_gen;

    // ---- init this group's state (both parity banks) ----
    if (lc < 16) {
        int i = lc*NTHR + tid;
        int gi = grp*6144 + i;
        g_h1[0][gi] = 0.f; g_h1[1][gi] = 0.f;
        g_h2[0][gi] = 0.f; g_h2[1][gi] = 0.f;
    }
    if (lc < 4) {
        int i = lc*NTHR + tid;
        if (i < 1408) g_prev[grp*1408 + i] = 0.f;
    }
    float creg1 = 0.f, creg2 = 0.f;    // private cell state (lane<8 valid)
    bt++; gbar(grp, bt);

    for (int t = 0; t < 510; t++) {
        int r = t & 1;
        float* h1new = g_h1[1-r];
        float* h2new = g_h2[1-r];

        // ===== phase A: layer-1 gates (K = prev(44) + h1old(192) = 236 fl4; ac part in g_Z) =====
        for (int i = tid; i < 8*236; i += NTHR) {
            int pg = i / 236, c = i - pg*236;
            int ba = b0 + 2*pg, bbq = ba+1;
            float4 a0, a1;
            if (c < 44) {
                a0 = __ldcg((const float4*)&g_prev[ba*176] + c);
                a1 = __ldcg((const float4*)&g_prev[bbq*176] + c);
            } else {
                a0 = __ldcg((const float4*)&g_h1[r][ba*768] + (c-44));
                a1 = __ldcg((const float4*)&g_h1[r][bbq*768] + (c-44));
            }
            int base = i*4;
            su[base+0] = pk2(a0.x, a1.x);
            su[base+1] = pk2(a0.y, a1.y);
            su[base+2] = pk2(a0.z, a1.z);
            su[base+3] = pk2(a0.w, a1.w);
        }
        __syncthreads();

        {
            ull acc2[4][4];
            #pragma unroll
            for (int g = 0; g < 4; g++)
                #pragma unroll
                for (int pl = 0; pl < 4; pl++) acc2[g][pl] = 0ull;

            float z4[4];
            if (lane < 8) {
                int m = (b0 + lane)*510 + t;
                #pragma unroll
                for (int g = 0; g < 4; g++)
                    z4[g] = __ldg(&g_Z[m*3072 + g*768 + jt]);
            }

            int c = lane;
            float4 w0 = __ldg(&wr1[c]);
            float4 w1 = __ldg(&wr1[236+c]);
            float4 w2 = __ldg(&wr1[472+c]);
            float4 w3 = __ldg(&wr1[708+c]);
            while (c < 236) {
                int cn = c + 32;
                float4 nw0=w0, nw1=w1, nw2=w2, nw3=w3;
                if (cn < 236) {
                    nw0 = __ldg(&wr1[cn]);      nw1 = __ldg(&wr1[236+cn]);
                    nw2 = __ldg(&wr1[472+cn]);  nw3 = __ldg(&wr1[708+cn]);
                }
                ull X[4][4];
                #pragma unroll
                for (int pl = 0; pl < 4; pl++) {
                    int base = (pl*236 + c)*4;
                    ulonglong2 xa = *(const ulonglong2*)&su[base];
                    ulonglong2 xb = *(const ulonglong2*)&su[base+2];
                    X[pl][0]=xa.x; X[pl][1]=xa.y; X[pl][2]=xb.x; X[pl][3]=xb.y;
                }
                {
                    ull d0=pk2(w0.x,w0.x), d1=pk2(w0.y,w0.y), d2=pk2(w0.z,w0.z), d3=pk2(w0.w,w0.w);
                    #pragma unroll
                    for (int pl = 0; pl < 4; pl++) {
                        fma2(acc2[0][pl], X[pl][0], d0); fma2(acc2[0][pl], X[pl][1], d1);
                        fma2(acc2[0][pl], X[pl][2], d2); fma2(acc2[0][pl], X[pl][3], d3);
                    }
                }
                {
                    ull d0=pk2(w1.x,w1.x), d1=pk2(w1.y,w1.y), d2=pk2(w1.z,w1.z), d3=pk2(w1.w,w1.w);
                    #pragma unroll
                    for (int pl = 0; pl < 4; pl++) {
                        fma2(acc2[1][pl], X[pl][0], d0); fma2(acc2[1][pl], X[pl][1], d1);
                        fma2(acc2[1][pl], X[pl][2], d2); fma2(acc2[1][pl], X[pl][3], d3);
                    }
                }
                {
                    ull d0=pk2(w2.x,w2.x), d1=pk2(w2.y,w2.y), d2=pk2(w2.z,w2.z), d3=pk2(w2.w,w2.w);
                    #pragma unroll
                    for (int pl = 0; pl < 4; pl++) {
                        fma2(acc2[2][pl], X[pl][0], d0); fma2(acc2[2][pl], X[pl][1], d1);
                        fma2(acc2[2][pl], X[pl][2], d2); fma2(acc2[2][pl], X[pl][3], d3);
                    }
                }
                {
                    ull d0=pk2(w3.x,w3.x), d1=pk2(w3.y,w3.y), d2=pk2(w3.z,w3.z), d3=pk2(w3.w,w3.w);
                    #pragma unroll
                    for (int pl = 0; pl < 4; pl++) {
                        fma2(acc2[3][pl], X[pl][0], d0); fma2(acc2[3][pl], X[pl][1], d1);
                        fma2(acc2[3][pl], X[pl][2], d2); fma2(acc2[3][pl], X[pl][3], d3);
                    }
                }
                w0=nw0; w1=nw1; w2=nw2; w3=nw3;
                c = cn;
            }
            #pragma unroll
            for (int off = 16; off; off >>= 1)
                #pragma unroll
                for (int g = 0; g < 4; g++)
                    #pragma unroll
                    for (int pl = 0; pl < 4; pl++) {
                        ull o = __shfl_xor_sync(0xffffffffu, acc2[g][pl], off);
                        add2(acc2[g][pl], o);
                    }
            if (lane < 8) {
                int pl = lane >> 1, hb = lane & 1;
                float zz[4];
                #pragma unroll
                for (int g = 0; g < 4; g++) {
                    float lo, hi; upk2(lo, hi, acc2[g][pl]);
                    zz[g] = (hb ? hi : lo) + z4[g];
                }
                float c_ = sigf(zz[1])*creg1 + sigf(zz[0])*tanhf(zz[2]);
                creg1 = c_;
                strel(&h1new[(b0 + lane)*768 + jt], sigf(zz[3])*tanhf(c_));
            }
        }
        bt++; gbar(grp, bt);

        // ===== phase B: layer-2 gates (K = h1new(192) + h2old(192) = 384 fl4) =====
        for (int i = tid; i < 8*384; i += NTHR) {
            int pg = i / 384, c = i - pg*384;
            int ba = b0 + 2*pg, bbq = ba+1;
            float4 a0, a1;
            if (c < 192) {
                a0 = __ldcg((const float4*)&h1new[ba*768] + c);
                a1 = __ldcg((const float4*)&h1new[bbq*768] + c);
            } else {
                a0 = __ldcg((const float4*)&g_h2[r][ba*768] + (c-192));
                a1 = __ldcg((const float4*)&g_h2[r][bbq*768] + (c-192));
            }
            int base = i*4;
            su[base+0] = pk2(a0.x, a1.x);
            su[base+1] = pk2(a0.y, a1.y);
            su[base+2] = pk2(a0.z, a1.z);
            su[base+3] = pk2(a0.w, a1.w);
        }
        __syncthreads();

        {
            ull acc2[4][4];
            #pragma unroll
            for (int g = 0; g < 4; g++)
                #pragma unroll
                for (int pl = 0; pl < 4; pl++) acc2[g][pl] = 0ull;

            float bsum[4];
            if (lane < 8) {
                #pragma unroll
                for (int g = 0; g < 4; g++)
                    bsum[g] = __ldg(&bih1[jt + g*768]) + __ldg(&bhh1[jt + g*768]);
            }

            int c = lane;
            float4 w0 = __ldg(&wr2[c]);
            float4 w1 = __ldg(&wr2[384+c]);
            float4 w2 = __ldg(&wr2[768+c]);
            float4 w3 = __ldg(&wr2[1152+c]);
            while (c < 384) {
                int cn = c + 32;
                float4 nw0=w0, nw1=w1, nw2=w2, nw3=w3;
                if (cn < 384) {
                    nw0 = __ldg(&wr2[cn]);       nw1 = __ldg(&wr2[384+cn]);
                    nw2 = __ldg(&wr2[768+cn]);   nw3 = __ldg(&wr2[1152+cn]);
                }
                ull X[4][4];
                #pragma unroll
                for (int pl = 0; pl < 4; pl++) {
                    int base = (pl*384 + c)*4;
                    ulonglong2 xa = *(const ulonglong2*)&su[base];
                    ulonglong2 xb = *(const ulonglong2*)&su[base+2];
                    X[pl][0]=xa.x; X[pl][1]=xa.y; X[pl][2]=xb.x; X[pl][3]=xb.y;
                }
                {
                    ull d0=pk2(w0.x,w0.x), d1=pk2(w0.y,w0.y), d2=pk2(w0.z,w0.z), d3=pk2(w0.w,w0.w);
                    #pragma unroll
                    for (int pl = 0; pl < 4; pl++) {
                        fma2(acc2[0][pl], X[pl][0], d0); fma2(acc2[0][pl], X[pl][1], d1);
                        fma2(acc2[0][pl], X[pl][2], d2); fma2(acc2[0][pl], X[pl][3], d3);
                    }
                }
                {
                    ull d0=pk2(w1.x,w1.x), d1=pk2(w1.y,w1.y), d2=pk2(w1.z,w1.z), d3=pk2(w1.w,w1.w);
                    #pragma unroll
                    for (int pl = 0; pl < 4; pl++) {
                        fma2(acc2[1][pl], X[pl][0], d0); fma2(acc2[1][pl], X[pl][1], d1);
                        fma2(acc2[1][pl], X[pl][2], d2); fma2(acc2[1][pl], X[pl][3], d3);
                    }
                }
                {
                    ull d0=pk2(w2.x,w2.x), d1=pk2(w2.y,w2.y), d2=pk2(w2.z,w2.z), d3=pk2(w2.w,w2.w);
                    #pragma unroll
                    for (int pl = 0; pl < 4; pl++) {
                        fma2(acc2[2][pl], X[pl][0], d0); fma2(acc2[2][pl], X[pl][1], d1);
                        fma2(acc2[2][pl], X[pl][2], d2); fma2(acc2[2][pl], X[pl][3], d3);
                    }
                }
                {
                    ull d0=pk2(w3.x,w3.x), d1=pk2(w3.y,w3.y), d2=pk2(w3.z,w3.z), d3=pk2(w3.w,w3.w);
                    #pragma unroll
                    for (int pl = 0; pl < 4; pl++) {
                        fma2(acc2[3][pl], X[pl][0], d0); fma2(acc2[3][pl], X[pl][1], d1);
                        fma2(acc2[3][pl], X[pl][2], d2); fma2(acc2[3][pl], X[pl][3], d3);
                    }
                }
                w0=nw0; w1=nw1; w2=nw2; w3=nw3;
                c = cn;
            }
            #pragma unroll
            for (int off = 16; off; off >>= 1)
                #pragma unroll
                for (int g = 0; g < 4; g++)
                    #pragma unroll
                    for (int pl = 0; pl < 4; pl++) {
                        ull o = __shfl_xor_sync(0xffffffffu, acc2[g][pl], off);
                        add2(acc2[g][pl], o);
                    }
            if (lane < 8) {
                int pl = lane >> 1, hb = lane & 1;
                float zz[4];
                #pragma unroll
                for (int g = 0; g < 4; g++) {
                    float lo, hi; upk2(lo, hi, acc2[g][pl]);
                    zz[g] = (hb ? hi : lo) + bsum[g];
                }
                float c_ = sigf(zz[1])*creg2 + sigf(zz[0])*tanhf(zz[2]);
                creg2 = c_;
                strel(&h2new[(b0 + lane)*768 + jt], sigf(zz[3])*tanhf(c_));
            }
        }
        bt++; gbar(grp, bt);

        // ===== phase C: projection + argmax + embedding feedback (group's 8 batches) =====
        for (int i = tid; i < 1536; i += NTHR)
            xs4[i] = __ldcg((const float4*)&h2new[b0*768] + i);
        __syncthreads();

        {
            int gwl = lc*12 + warp;            // 0..767
            if (gwl < 704) {
                int bl = gwl / 88, p = gwl - bl*88;
                int b = b0 + bl;
                float a0=0.f, a1=0.f, a2=0.f, a3=0.f, a4=0.f;
                for (int c = lane; c < 192; c += 32) {
                    float4 x = xs4[bl*192 + c];
                    float4 v0 = __ldg(&pw4[(p*5+0)*192 + c]);
                    float4 v1 = __ldg(&pw4[(p*5+1)*192 + c]);
                    float4 v2 = __ldg(&pw4[(p*5+2)*192 + c]);
                    float4 v3 = __ldg(&pw4[(p*5+3)*192 + c]);
                    float4 v4 = __ldg(&pw4[(p*5+4)*192 + c]);
                    a0 = fmaf(x.x,v0.x, fmaf(x.y,v0.y, fmaf(x.z,v0.z, fmaf(x.w,v0.w, a0))));
                    a1 = fmaf(x.x,v1.x, fmaf(x.y,v1.y, fmaf(x.z,v1.z, fmaf(x.w,v1.w, a1))));
                    a2 = fmaf(x.x,v2.x, fmaf(x.y,v2.y, fmaf(x.z,v2.z, fmaf(x.w,v2.w, a2))));
                    a3 = fmaf(x.x,v3.x, fmaf(x.y,v3.y, fmaf(x.z,v3.z, fmaf(x.w,v3.w, a3))));
                    a4 = fmaf(x.x,v4.x, fmaf(x.y,v4.y, fmaf(x.z,v4.z, fmaf(x.w,v4.w, a4))));
                }
                #pragma unroll
                for (int off = 16; off; off >>= 1) {
                    a0 += __shfl_xor_sync(0xffffffffu, a0, off);
                    a1 += __shfl_xor_sync(0xffffffffu, a1, off);
                    a2 += __shfl_xor_sync(0xffffffffu, a2, off);
                    a3 += __shfl_xor_sync(0xffffffffu, a3, off);
                    a4 += __shfl_xor_sync(0xffffffffu, a4, off);
                }
                if (lane == 0) {
                    float l0 = a0 + pb[p*5+0];
                    float l1 = a1 + pb[p*5+1];
                    float l2 = a2 + pb[p*5+2];
                    float l3 = a3 + pb[p*5+3];
                    float l4 = a4 + pb[p*5+4];
                    float* o = &out[((b*510 + t)*88 + p)*5];
                    o[0]=l0; o[1]=l1; o[2]=l2; o[3]=l3; o[4]=l4;
                    float best = l0; int bi = 0;
                    if (l1 > best) { best = l1; bi = 1; }
                    if (l2 > best) { best = l2; bi = 2; }
                    if (l3 > best) { best = l3; bi = 3; }
                    if (l4 > best) { best = l4; bi = 4; }
                    strel2(&g_prev[b*176 + p*2], emb[bi*2], emb[bi*2 + 1]);
                }
            }
        }
        bt++; gbar(grp, bt);
    }

    if (cta == 0 && tid == 0) g_gen = bt;
}

// =================== host ===================
extern "C" void kernel_launch(void* const* d_in, const int* in_sizes, int n_in,
                              void* d_out, int out_size)
{
    const float* mel  = (const float*)d_in[0];
    const float* c1w  = (const float*)d_in[1];
    const float* c1b  = (const float*)d_in[2];
    const float* c2w  = (const float*)d_in[3];
    const float* c2b  = (const float*)d_in[4];
    const float* c3w  = (const float*)d_in[5];
    const float* c3b  = (const float*)d_in[6];
    const float* bn1g = (const float*)d_in[7],  *bn1b = (const float*)d_in[8];
    const float* bn1m = (const float*)d_in[9],  *bn1v = (const float*)d_in[10];
    const float* bn2g = (const float*)d_in[11], *bn2b = (const float*)d_in[12];
    const float* bn2m = (const float*)d_in[13], *bn2v = (const float*)d_in[14];
    const float* bn3g = (const float*)d_in[15], *bn3b = (const float*)d_in[16];
    const float* bn3m = (const float*)d_in[17], *bn3v = (const float*)d_in[18];
    const float* fcw  = (const float*)d_in[19], *fcb  = (const float*)d_in[20];
    const float* wih0 = (const float*)d_in[21], *whh0 = (const float*)d_in[22];
    const float* bih0 = (const float*)d_in[23], *bhh0 = (const float*)d_in[24];
    const float* wih1 = (const float*)d_in[25], *whh1 = (const float*)d_in[26];
    const float* bih1 = (const float*)d_in[27], *bhh1 = (const float*)d_in[28];
    const float* pw   = (const float*)d_in[29], *pb   = (const float*)d_in[30];
    const float* emb  = (const float*)d_in[31];
    float* out = (float*)d_out;

    float* d_gD  = nullptr;
    float* d_gac = nullptr;
    float* d_gZ  = nullptr;
    cudaGetSymbolAddress((void**)&d_gD,  g_D);
    cudaGetSymbolAddress((void**)&d_gac, g_ac);
    cudaGetSymbolAddress((void**)&d_gZ,  g_Z);

    cudaFuncSetAttribute((const void*)k_lstm,
                         cudaFuncAttributeMaxDynamicSharedMemorySize, 98304);

    k_pack1<<<(768*944 + 255)/256, 256>>>(wih0, whh0);
    k_pack2<<<(768*1536 + 255)/256, 256>>>(wih1, whh1);
    k_conv1<<<(16*512*229 + 255)/256, 256>>>(mel, c1w, c1b, bn1g, bn1b, bn1m, bn1v);
    k_conv2pool<<<16*256*4, 256>>>(c2w, c2b, bn2g, bn2b, bn2m, bn2v);
    k_conv3pool<<<16*255*8, 256>>>(c3w, c3b, bn3g, bn3b, bn3m, bn3v);
    // FC: acoustic = g_D @ fcw^T + fcb   (M=8160, N=768, K=5472)
    k_gemm<<<dim3(6, 64), 256>>>(d_gD, 5472, fcw, 5472, fcb, nullptr,
                                 d_gac, 768, 8160, 5472);
    // Z: g_Z = g_ac @ wih0[:, :768]^T + bih0 + bhh0  (M=8160, N=3072, K=768)
    k_gemm<<<dim3(24, 64), 256>>>(d_gac, 768, wih0, 944, bih0, bhh0,
                                  d_gZ, 3072, 8160, 768);
    k_lstm<<<NCTA, NTHR, 98304>>>(bih1, bhh1, pw, pb, emb, out);
}